// round 1
// baseline (speedup 1.0000x reference)
#include <cuda_runtime.h>
#include <math.h>

// ---------------- problem constants ----------------
#define T_    2048
#define DIM_  2048
#define QL_   1536
#define H_    16
#define DH_   256
#define NOPE_ 192
#define HI_   32
#define DI_   128
#define INOPE_ 64
#define SC_   512
#define TOPK_ 256
#define II_   8192
#define G_    4
#define OLORA_ 512
#define EPSF  1e-6f
#define NEGF  (-1e30f)
#define SCALE_   0.0625f                 // 256^-0.5
#define ISCALE_  0.08838834764831845f    // 128^-0.5
#define LOG_THETA 11.98292909421596506   // ln(160000)

// ---------------- scratch (device globals; no cudaMalloc allowed) ----------------
__device__ float g_x   [T_ * DIM_];
__device__ float g_qr  [T_ * QL_];
__device__ float g_q   [T_ * H_ * DH_];
__device__ float g_qi  [T_ * HI_ * DI_];
__device__ float g_kvA [T_ * 2 * DH_];
__device__ float g_kvG [T_ * 2 * DH_];
__device__ float g_kvF [T_ * 2 * DH_];
__device__ float g_kvc [SC_ * DH_];
__device__ float g_ikA [T_ * 2 * DI_];
__device__ float g_ikG [T_ * 2 * DI_];
__device__ float g_ikF [T_ * 2 * DI_];
__device__ float g_ki  [SC_ * DI_];
__device__ float g_iw  [T_ * HI_];
__device__ float g_R   [(size_t)T_ * HI_ * SC_];   // 134 MB
__device__ float g_isc [T_ * SC_];
__device__ int   g_selidx[T_ * TOPK_];
__device__ int   g_selcnt[T_];
__device__ float g_o   [T_ * H_ * DH_];
__device__ float g_oa  [T_ * G_ * OLORA_];
__device__ float g_h   [T_ * DIM_];
__device__ float g_x2  [T_ * DIM_];
__device__ float g_gu  [(size_t)T_ * 2 * II_];     // 128 MB
__device__ float g_act [(size_t)T_ * II_];

// ---------------- block reductions ----------------
__device__ __forceinline__ float blockReduceSum(float v) {
    __shared__ float sh[32];
    int lane = threadIdx.x & 31, wid = threadIdx.x >> 5;
    #pragma unroll
    for (int o = 16; o > 0; o >>= 1) v += __shfl_xor_sync(0xffffffffu, v, o);
    if (lane == 0) sh[wid] = v;
    __syncthreads();
    int nw = (blockDim.x + 31) >> 5;
    if (wid == 0) {
        float r = (lane < nw) ? sh[lane] : 0.0f;
        #pragma unroll
        for (int o = 16; o > 0; o >>= 1) r += __shfl_xor_sync(0xffffffffu, r, o);
        if (lane == 0) sh[0] = r;
    }
    __syncthreads();
    float res = sh[0];
    __syncthreads();
    return res;
}

__device__ __forceinline__ float blockReduceMax(float v) {
    __shared__ float sh[32];
    int lane = threadIdx.x & 31, wid = threadIdx.x >> 5;
    #pragma unroll
    for (int o = 16; o > 0; o >>= 1) v = fmaxf(v, __shfl_xor_sync(0xffffffffu, v, o));
    if (lane == 0) sh[wid] = v;
    __syncthreads();
    int nw = (blockDim.x + 31) >> 5;
    if (wid == 0) {
        float r = (lane < nw) ? sh[lane] : -3.4e38f;
        #pragma unroll
        for (int o = 16; o > 0; o >>= 1) r = fmaxf(r, __shfl_xor_sync(0xffffffffu, r, o));
        if (lane == 0) sh[0] = r;
    }
    __syncthreads();
    float res = sh[0];
    __syncthreads();
    return res;
}

// ---------------- generic guarded SGEMM 128x128x8, 8x8/thread ----------------
#define BM 128
#define BN 128
#define BK 8
#define TM 8
#define TN 8

template<bool BT, bool ADD>
__global__ void __launch_bounds__(256, 2) sgemm_kernel(
    int M, int N, int K,
    const float* __restrict__ A, int lda,
    const float* __restrict__ B, int ldb,
    const float* __restrict__ Cadd,
    float* __restrict__ C, int ldc)
{
    __shared__ float As[BK][BM];
    __shared__ float Bs[BK][BN];
    int bm = blockIdx.y * BM;
    int bn = blockIdx.x * BN;
    int tid = threadIdx.x;
    int tx = tid & 15, ty = tid >> 4;
    float acc[TM][TN] = {};
    for (int k0 = 0; k0 < K; k0 += BK) {
        #pragma unroll
        for (int i = 0; i < 4; i++) {
            int idx = tid + i * 256;
            int r = idx >> 3, c = idx & 7;
            int gr = bm + r;
            As[c][r] = (gr < M) ? A[(size_t)gr * lda + (k0 + c)] : 0.0f;
        }
        #pragma unroll
        for (int i = 0; i < 4; i++) {
            int idx = tid + i * 256;
            if (!BT) {
                int r = idx >> 7, c = idx & 127;   // r in [0,8), c in [0,128)
                int gc = bn + c;
                Bs[r][c] = (gc < N) ? B[(size_t)(k0 + r) * ldb + gc] : 0.0f;
            } else {
                int c = idx >> 3, r = idx & 7;     // B is (N,K)
                int gn = bn + c;
                Bs[r][c] = (gn < N) ? B[(size_t)gn * ldb + (k0 + r)] : 0.0f;
            }
        }
        __syncthreads();
        #pragma unroll
        for (int k = 0; k < BK; k++) {
            float ra[TM], rb[TN];
            #pragma unroll
            for (int i = 0; i < TM; i++) ra[i] = As[k][ty * TM + i];
            #pragma unroll
            for (int j = 0; j < TN; j++) rb[j] = Bs[k][tx * TN + j];
            #pragma unroll
            for (int i = 0; i < TM; i++)
                #pragma unroll
                for (int j = 0; j < TN; j++)
                    acc[i][j] += ra[i] * rb[j];
        }
        __syncthreads();
    }
    #pragma unroll
    for (int i = 0; i < TM; i++) {
        int gm = bm + ty * TM + i;
        if (gm >= M) continue;
        #pragma unroll
        for (int j = 0; j < TN; j++) {
            int gn = bn + tx * TN + j;
            if (gn >= N) continue;
            float v = acc[i][j];
            if (ADD) v += Cadd[(size_t)gm * ldc + gn];
            C[(size_t)gm * ldc + gn] = v;
        }
    }
}

// ---------------- rmsnorm (block per row) ----------------
__global__ void rms_kernel(const float* __restrict__ in, const float* __restrict__ w,
                           float* __restrict__ out, int D)
{
    int t = blockIdx.x;
    const float* row = in + (size_t)t * D;
    float s = 0.0f;
    for (int d = threadIdx.x; d < D; d += blockDim.x) { float v = row[d]; s += v * v; }
    s = blockReduceSum(s);
    float inv = rsqrtf(s / (float)D + EPSF);
    for (int d = threadIdx.x; d < D; d += blockDim.x)
        out[(size_t)t * D + d] = row[d] * inv * w[d];
}

// ---------------- kv gate + ape ----------------
__global__ void kvgate_kernel(const float* __restrict__ A, const float* __restrict__ Gt,
                              const float* __restrict__ ape, float* __restrict__ out, int W)
{
    int i = blockIdx.x * blockDim.x + threadIdx.x;
    if (i >= T_ * W) return;
    int t = i / W, e = i - t * W;
    float g = 1.0f / (1.0f + expf(-Gt[i]));
    out[i] = A[i] * g + ape[(t & 3) * W + e];
}

// ---------------- compress window mean + rms (block per compressed row) ----------------
__global__ void compress_kernel(const float* __restrict__ kvf, const float* __restrict__ w,
                                float* __restrict__ out, int d)
{
    int b = blockIdx.x;
    int e = threadIdx.x;     // blockDim.x == d
    int W = 2 * d;
    float m = 0.0f;
    if (b > 0) {
        #pragma unroll
        for (int r = 0; r < 4; r++) m += kvf[(size_t)((b - 1) * 4 + r) * W + e];
    }
    #pragma unroll
    for (int r = 0; r < 4; r++) m += kvf[(size_t)(b * 4 + r) * W + d + e];
    m *= 0.125f;
    float ssq = blockReduceSum(m * m);
    float inv = rsqrtf(ssq / (float)d + EPSF);
    out[(size_t)b * d + e] = m * inv * w[e];
}

// ---------------- interleaved RoPE on last 64 dims ----------------
__global__ void rope_kernel(float* __restrict__ x, const int* __restrict__ positions,
                            int Hh, int Dd, int ropeOff, int compPos)
{
    int th = blockIdx.x;
    int t = th / Hh;
    int i = threadIdx.x;  // 0..31 (pair index)
    float* p = x + ((size_t)th) * Dd + ropeOff;
    int pos = compPos ? (4 * (t + 1) - 1) : positions[t];
    double freq = exp(-((double)(2 * i) / 64.0) * LOG_THETA);
    double ang = (double)pos * freq;
    float c = (float)cos(ang), s = (float)sin(ang);
    float x0 = p[2 * i], x1 = p[2 * i + 1];
    p[2 * i]     = x0 * c - x1 * s;
    p[2 * i + 1] = x0 * s + x1 * c;
}

// ---------------- index score reduce: iscore[t,s] = ISCALE * sum_h iw[t,h]*relu(R[t,h,s]) ----------------
__global__ void iscore_reduce_kernel(const float* __restrict__ R, const float* __restrict__ iw,
                                     float* __restrict__ isc)
{
    int t = blockIdx.x;
    __shared__ float ws[HI_];
    if (threadIdx.x < HI_) ws[threadIdx.x] = iw[t * HI_ + threadIdx.x];
    __syncthreads();
    for (int s = threadIdx.x; s < SC_; s += blockDim.x) {
        const float* Rp = R + (size_t)t * HI_ * SC_ + s;
        float acc = 0.0f;
        #pragma unroll
        for (int h = 0; h < HI_; h++)
            acc += ws[h] * fmaxf(Rp[(size_t)h * SC_], 0.0f);
        isc[t * SC_ + s] = acc * ISCALE_;
    }
}

// ---------------- exact top-256 per token (bitonic sort of 512, tie: lower index) ----------------
__global__ void topk_kernel(const float* __restrict__ isc, int* __restrict__ selidx,
                            int* __restrict__ selcnt)
{
    int t = blockIdx.x;
    __shared__ float sv[SC_];
    __shared__ int   si[SC_];
    int tid = threadIdx.x;   // 256 threads
    int visCount = (t >= 3) ? ((t - 3) / 4 + 1) : 0;
    for (int i = tid; i < SC_; i += 256) {
        sv[i] = (i < visCount) ? isc[t * SC_ + i] : NEGF;
        si[i] = i;
    }
    __syncthreads();
    for (int k = 2; k <= SC_; k <<= 1) {
        for (int j = k >> 1; j > 0; j >>= 1) {
            for (int base = tid; base < SC_; base += 256) {
                int partner = base ^ j;
                if (partner > base) {
                    bool up = ((base & k) == 0);
                    float va = sv[base], vb = sv[partner];
                    int ia = si[base], ib = si[partner];
                    bool aFirst = (va > vb) || (va == vb && ia < ib);
                    if (up ? !aFirst : aFirst) {
                        sv[base] = vb; sv[partner] = va;
                        si[base] = ib; si[partner] = ia;
                    }
                }
            }
            __syncthreads();
        }
    }
    int cnt = min(visCount, TOPK_);
    if (tid == 0) selcnt[t] = cnt;
    for (int r = tid; r < cnt; r += 256) selidx[t * TOPK_ + r] = si[r];
}

// ---------------- sparse attention over selected rows + sink ----------------
__global__ void attn_kernel(const float* __restrict__ q, const float* __restrict__ kvc,
                            const int* __restrict__ selidx, const int* __restrict__ selcnt,
                            const float* __restrict__ sink, float* __restrict__ o)
{
    int h = blockIdx.x, t = blockIdx.y;
    int tid = threadIdx.x;   // 256 threads, DH_ == 256
    __shared__ float qs[DH_];
    __shared__ float pl[TOPK_];
    __shared__ int   ss[TOPK_];
    int cnt = selcnt[t];
    qs[tid] = q[((size_t)t * H_ + h) * DH_ + tid];
    if (tid < cnt) ss[tid] = selidx[t * TOPK_ + tid];
    __syncthreads();

    float lg = NEGF;
    if (tid < cnt) {
        const float4* kr = (const float4*)(kvc + (size_t)ss[tid] * DH_);
        const float4* qr = (const float4*)qs;
        float dot = 0.0f;
        #pragma unroll 16
        for (int i = 0; i < DH_ / 4; i++) {
            float4 a = qr[i], b = kr[i];
            dot += a.x * b.x + a.y * b.y + a.z * b.z + a.w * b.w;
        }
        lg = dot * SCALE_;
    }
    float m = blockReduceMax(lg);
    float snk = sink[h];
    m = fmaxf(m, snk);
    float e = (tid < cnt) ? expf(lg - m) : 0.0f;
    float denom = blockReduceSum(e) + expf(snk - m);
    if (tid < cnt) pl[tid] = e / denom;
    __syncthreads();

    float acc = 0.0f;
    for (int j = 0; j < cnt; j++)
        acc += pl[j] * kvc[(size_t)ss[j] * DH_ + tid];
    o[((size_t)t * H_ + h) * DH_ + tid] = acc;
}

// ---------------- silu-gate ----------------
__global__ void silu_kernel(const float* __restrict__ gu, float* __restrict__ act)
{
    size_t i = (size_t)blockIdx.x * blockDim.x + threadIdx.x;
    if (i >= (size_t)T_ * II_) return;
    size_t t = i / II_, c = i - t * II_;
    float a = gu[t * (2 * II_) + c];
    float b = gu[t * (2 * II_) + II_ + c];
    act[i] = a / (1.0f + expf(-a)) * b;
}

// ---------------- host launch ----------------
static inline dim3 ggrid(int M, int N) { return dim3((N + BN - 1) / BN, (M + BM - 1) / BM); }

extern "C" void kernel_launch(void* const* d_in, const int* in_sizes, int n_in,
                              void* d_out, int out_size)
{
    const float* hidden      = (const float*)d_in[0];
    const int*   positions   = (const int*)  d_in[1];
    const float* ln1_w       = (const float*)d_in[2];
    const float* ln2_w       = (const float*)d_in[3];
    const float* wq_a        = (const float*)d_in[4];
    const float* q_norm_w    = (const float*)d_in[5];
    const float* wq_b        = (const float*)d_in[6];
    const float* comp_wkv    = (const float*)d_in[7];
    const float* comp_wgate  = (const float*)d_in[8];
    const float* comp_ape    = (const float*)d_in[9];
    const float* comp_norm_w = (const float*)d_in[10];
    const float* idx_wq_b    = (const float*)d_in[11];
    const float* idx_wproj   = (const float*)d_in[12];
    const float* icomp_wkv   = (const float*)d_in[13];
    const float* icomp_wgate = (const float*)d_in[14];
    const float* icomp_ape   = (const float*)d_in[15];
    const float* icomp_norm_w= (const float*)d_in[16];
    const float* attn_sink   = (const float*)d_in[17];
    const float* wo_a        = (const float*)d_in[18];
    const float* wo_b        = (const float*)d_in[19];
    const float* gate_up_w   = (const float*)d_in[20];
    const float* down_w      = (const float*)d_in[21];
    float* out = (float*)d_out;

    float *px, *pqr, *pq, *pqi, *pkvA, *pkvG, *pkvF, *pkvc;
    float *pikA, *pikG, *pikF, *pki, *piw, *pR, *pisc, *po, *poa, *ph, *px2, *pgu, *pact;
    int *pselidx, *pselcnt;
    cudaGetSymbolAddress((void**)&px,   g_x);
    cudaGetSymbolAddress((void**)&pqr,  g_qr);
    cudaGetSymbolAddress((void**)&pq,   g_q);
    cudaGetSymbolAddress((void**)&pqi,  g_qi);
    cudaGetSymbolAddress((void**)&pkvA, g_kvA);
    cudaGetSymbolAddress((void**)&pkvG, g_kvG);
    cudaGetSymbolAddress((void**)&pkvF, g_kvF);
    cudaGetSymbolAddress((void**)&pkvc, g_kvc);
    cudaGetSymbolAddress((void**)&pikA, g_ikA);
    cudaGetSymbolAddress((void**)&pikG, g_ikG);
    cudaGetSymbolAddress((void**)&pikF, g_ikF);
    cudaGetSymbolAddress((void**)&pki,  g_ki);
    cudaGetSymbolAddress((void**)&piw,  g_iw);
    cudaGetSymbolAddress((void**)&pR,   g_R);
    cudaGetSymbolAddress((void**)&pisc, g_isc);
    cudaGetSymbolAddress((void**)&pselidx, g_selidx);
    cudaGetSymbolAddress((void**)&pselcnt, g_selcnt);
    cudaGetSymbolAddress((void**)&po,   g_o);
    cudaGetSymbolAddress((void**)&poa,  g_oa);
    cudaGetSymbolAddress((void**)&ph,   g_h);
    cudaGetSymbolAddress((void**)&px2,  g_x2);
    cudaGetSymbolAddress((void**)&pgu,  g_gu);
    cudaGetSymbolAddress((void**)&pact, g_act);

    // 1) x = rms(hidden, ln1)
    rms_kernel<<<T_, 256>>>(hidden, ln1_w, px, DIM_);

    // 2) qr = rms(x @ wq_a, q_norm)
    sgemm_kernel<false,false><<<ggrid(T_, QL_), 256>>>(T_, QL_, DIM_, px, DIM_, wq_a, QL_, nullptr, pqr, QL_);
    rms_kernel<<<T_, 256>>>(pqr, q_norm_w, pqr, QL_);

    // 3) q = qr @ wq_b ; qi = qr @ idx_wq_b ; rope both
    sgemm_kernel<false,false><<<ggrid(T_, H_*DH_), 256>>>(T_, H_*DH_, QL_, pqr, QL_, wq_b, H_*DH_, nullptr, pq, H_*DH_);
    sgemm_kernel<false,false><<<ggrid(T_, HI_*DI_), 256>>>(T_, HI_*DI_, QL_, pqr, QL_, idx_wq_b, HI_*DI_, nullptr, pqi, HI_*DI_);
    rope_kernel<<<T_ * H_,  32>>>(pq,  positions, H_,  DH_, NOPE_,  0);
    rope_kernel<<<T_ * HI_, 32>>>(pqi, positions, HI_, DI_, INOPE_, 0);

    // 4) kvc = compress(x, comp_*) + rope
    sgemm_kernel<false,false><<<ggrid(T_, 2*DH_), 256>>>(T_, 2*DH_, DIM_, px, DIM_, comp_wkv,   2*DH_, nullptr, pkvA, 2*DH_);
    sgemm_kernel<false,false><<<ggrid(T_, 2*DH_), 256>>>(T_, 2*DH_, DIM_, px, DIM_, comp_wgate, 2*DH_, nullptr, pkvG, 2*DH_);
    kvgate_kernel<<<(T_ * 2 * DH_ + 255) / 256, 256>>>(pkvA, pkvG, comp_ape, pkvF, 2*DH_);
    compress_kernel<<<SC_, DH_>>>(pkvF, comp_norm_w, pkvc, DH_);
    rope_kernel<<<SC_, 32>>>(pkvc, nullptr, 1, DH_, NOPE_, 1);

    // 5) ki = compress(x, icomp_*) + rope
    sgemm_kernel<false,false><<<ggrid(T_, 2*DI_), 256>>>(T_, 2*DI_, DIM_, px, DIM_, icomp_wkv,   2*DI_, nullptr, pikA, 2*DI_);
    sgemm_kernel<false,false><<<ggrid(T_, 2*DI_), 256>>>(T_, 2*DI_, DIM_, px, DIM_, icomp_wgate, 2*DI_, nullptr, pikG, 2*DI_);
    kvgate_kernel<<<(T_ * 2 * DI_ + 255) / 256, 256>>>(pikA, pikG, icomp_ape, pikF, 2*DI_);
    compress_kernel<<<SC_, DI_>>>(pikF, icomp_norm_w, pki, DI_);
    rope_kernel<<<SC_, 32>>>(pki, nullptr, 1, DI_, INOPE_, 1);

    // 6) iw = x @ idx_weights_proj
    sgemm_kernel<false,false><<<ggrid(T_, HI_), 256>>>(T_, HI_, DIM_, px, DIM_, idx_wproj, HI_, nullptr, piw, HI_);

    // 7) R = qi @ ki^T  (view qi as (T*HI, DI)); then iscore reduce
    sgemm_kernel<true,false><<<ggrid(T_*HI_, SC_), 256>>>(T_*HI_, SC_, DI_, pqi, DI_, pki, DI_, nullptr, pR, SC_);
    iscore_reduce_kernel<<<T_, 256>>>(pR, piw, pisc);

    // 8) exact top-256 per token
    topk_kernel<<<T_, 256>>>(pisc, pselidx, pselcnt);

    // 9) sparse attention
    attn_kernel<<<dim3(H_, T_), DH_>>>(pq, pkvc, pselidx, pselcnt, attn_sink, po);

    // 10) oa (4 grouped GEMMs, B transposed), then h = res + oa @ wo_b
    for (int g = 0; g < G_; g++) {
        sgemm_kernel<true,false><<<ggrid(T_, OLORA_), 256>>>(
            T_, OLORA_, (H_/G_)*DH_,
            po + g * (H_/G_)*DH_, H_*DH_,
            wo_a + (size_t)g * OLORA_ * (H_/G_)*DH_, (H_/G_)*DH_,
            nullptr, poa + g * OLORA_, G_*OLORA_);
    }
    sgemm_kernel<false,true><<<ggrid(T_, DIM_), 256>>>(T_, DIM_, G_*OLORA_, poa, G_*OLORA_, wo_b, DIM_, hidden, ph, DIM_);

    // 11) MLP: x2 = rms(h); gu = x2 @ gate_up; act = silu(gu_l)*gu_r; out = h + act @ down
    rms_kernel<<<T_, 256>>>(ph, ln2_w, px2, DIM_);
    sgemm_kernel<false,false><<<ggrid(T_, 2*II_), 256>>>(T_, 2*II_, DIM_, px2, DIM_, gate_up_w, 2*II_, nullptr, pgu, 2*II_);
    silu_kernel<<<(int)(((size_t)T_ * II_ + 255) / 256), 256>>>(pgu, pact);
    sgemm_kernel<false,true><<<ggrid(T_, DIM_), 256>>>(T_, DIM_, II_, pact, II_, down_w, DIM_, ph, out, DIM_);
}

// round 2
// speedup vs baseline: 2.3290x; 2.3290x over previous
#include <cuda_runtime.h>
#include <math.h>
#include <stdint.h>

// ---------------- problem constants ----------------
#define T_    2048
#define DIM_  2048
#define QL_   1536
#define H_    16
#define DH_   256
#define NOPE_ 192
#define HI_   32
#define DI_   128
#define INOPE_ 64
#define SC_   512
#define TOPK_ 256
#define II_   8192
#define G_    4
#define OLORA_ 512
#define EPSF  1e-6f
#define NEGF  (-1e30f)
#define SCALE_   0.0625f
#define ISCALE_  0.08838834764831845f
#define LOG_THETA 11.98292909421596506

// ---------------- scratch ----------------
__device__ float g_x   [T_ * DIM_];
__device__ float g_qr  [T_ * QL_];
__device__ float g_q   [T_ * H_ * DH_];
__device__ float g_qi  [T_ * HI_ * DI_];
__device__ float g_kvA [T_ * 2 * DH_];
__device__ float g_kvG [T_ * 2 * DH_];
__device__ float g_kvF [T_ * 2 * DH_];
__device__ float g_kvc [SC_ * DH_];
__device__ float g_ikA [T_ * 2 * DI_];
__device__ float g_ikG [T_ * 2 * DI_];
__device__ float g_ikF [T_ * 2 * DI_];
__device__ float g_ki  [SC_ * DI_];
__device__ float g_iw  [T_ * HI_];
__device__ float g_R   [(size_t)T_ * HI_ * SC_];
__device__ float g_isc [T_ * SC_];
__device__ int   g_selidx[T_ * TOPK_];
__device__ int   g_selcnt[T_];
__device__ float g_o   [T_ * H_ * DH_];
__device__ float g_oa  [T_ * G_ * OLORA_];
__device__ float g_h   [T_ * DIM_];
__device__ float g_x2  [T_ * DIM_];
__device__ float g_gu  [(size_t)T_ * 2 * II_];
__device__ float g_act [(size_t)T_ * II_];

// ---------------- reductions ----------------
__device__ __forceinline__ float blockReduceSum(float v) {
    __shared__ float sh[32];
    int lane = threadIdx.x & 31, wid = threadIdx.x >> 5;
    #pragma unroll
    for (int o = 16; o > 0; o >>= 1) v += __shfl_xor_sync(0xffffffffu, v, o);
    if (lane == 0) sh[wid] = v;
    __syncthreads();
    int nw = (blockDim.x + 31) >> 5;
    if (wid == 0) {
        float r = (lane < nw) ? sh[lane] : 0.0f;
        #pragma unroll
        for (int o = 16; o > 0; o >>= 1) r += __shfl_xor_sync(0xffffffffu, r, o);
        if (lane == 0) sh[0] = r;
    }
    __syncthreads();
    float res = sh[0];
    __syncthreads();
    return res;
}

__device__ __forceinline__ float blockReduceMax(float v) {
    __shared__ float sh[32];
    int lane = threadIdx.x & 31, wid = threadIdx.x >> 5;
    #pragma unroll
    for (int o = 16; o > 0; o >>= 1) v = fmaxf(v, __shfl_xor_sync(0xffffffffu, v, o));
    if (lane == 0) sh[wid] = v;
    __syncthreads();
    int nw = (blockDim.x + 31) >> 5;
    if (wid == 0) {
        float r = (lane < nw) ? sh[lane] : -3.4e38f;
        #pragma unroll
        for (int o = 16; o > 0; o >>= 1) r = fmaxf(r, __shfl_xor_sync(0xffffffffu, r, o));
        if (lane == 0) sh[0] = r;
    }
    __syncthreads();
    float res = sh[0];
    __syncthreads();
    return res;
}

// ---------------- tf32 helpers ----------------
__device__ __forceinline__ uint32_t f2tf32(float x) {
    uint32_t r;
    asm("cvt.rna.tf32.f32 %0, %1;" : "=r"(r) : "f"(x));
    return r;
}

__device__ __forceinline__ void mma_tf32(float* d, const uint32_t* a, const uint32_t* b) {
    asm volatile(
        "mma.sync.aligned.m16n8k8.row.col.f32.tf32.tf32.f32 "
        "{%0,%1,%2,%3}, {%4,%5,%6,%7}, {%8,%9}, {%0,%1,%2,%3};"
        : "+f"(d[0]), "+f"(d[1]), "+f"(d[2]), "+f"(d[3])
        : "r"(a[0]), "r"(a[1]), "r"(a[2]), "r"(a[3]), "r"(b[0]), "r"(b[1]));
}

// ---------------- tensor-core TF32 GEMM, 128x128x32, 8 warps ----------------
// C[M,N] = A[M,K] @ (BT ? B[N,K]^T : B[K,N]) (+ Cadd). K % 32 == 0, N % 4 == 0,
// lda/ldb % 4 == 0.
#define BM 128
#define BN 128
#define BK 32
#define AS_S 36
#define BS_S 137

template<bool BT, bool ADD>
__global__ void __launch_bounds__(256, 2) tgemm_kernel(
    int M, int N, int K,
    const float* __restrict__ A, int lda,
    const float* __restrict__ B, int ldb,
    const float* __restrict__ Cadd,
    float* __restrict__ C, int ldc)
{
    __shared__ uint32_t As[BM * AS_S];
    __shared__ uint32_t Bs[BK * BS_S];
    const int bm = blockIdx.y * BM;
    const int bn = blockIdx.x * BN;
    const int tid = threadIdx.x;
    const int lane = tid & 31;
    const int wid = tid >> 5;
    const int wm = wid & 3;         // 4 warps along M
    const int wn = wid >> 2;        // 2 warps along N
    const int gid = lane >> 2;      // 0..7
    const int tig = lane & 3;       // 0..3

    float acc[2][8][4];
    #pragma unroll
    for (int mi = 0; mi < 2; mi++)
        #pragma unroll
        for (int ni = 0; ni < 8; ni++)
            #pragma unroll
            for (int r = 0; r < 4; r++) acc[mi][ni][r] = 0.0f;

    for (int k0 = 0; k0 < K; k0 += BK) {
        // ---- load A tile: rows bm..+127, cols k0..+31 ----
        #pragma unroll
        for (int i = 0; i < 4; i++) {
            int f = tid + i * 256;
            int r = f >> 3, q = f & 7;
            int gr = bm + r;
            float4 v = make_float4(0.f, 0.f, 0.f, 0.f);
            if (gr < M) v = *(const float4*)(A + (size_t)gr * lda + k0 + 4 * q);
            uint32_t* dst = &As[r * AS_S + 4 * q];
            dst[0] = f2tf32(v.x); dst[1] = f2tf32(v.y);
            dst[2] = f2tf32(v.z); dst[3] = f2tf32(v.w);
        }
        // ---- load B tile into Bs[k][n] ----
        if (!BT) {
            #pragma unroll
            for (int i = 0; i < 4; i++) {
                int f = tid + i * 256;
                int k = f >> 5, q = f & 31;
                int gc = bn + 4 * q;
                float4 v = make_float4(0.f, 0.f, 0.f, 0.f);
                if (gc < N) v = *(const float4*)(B + (size_t)(k0 + k) * ldb + gc);
                uint32_t* dst = &Bs[k * BS_S + 4 * q];
                dst[0] = f2tf32(v.x); dst[1] = f2tf32(v.y);
                dst[2] = f2tf32(v.z); dst[3] = f2tf32(v.w);
            }
        } else {
            #pragma unroll
            for (int i = 0; i < 4; i++) {
                int f = tid + i * 256;
                int n = f >> 3, q = f & 7;
                int gn = bn + n;
                float4 v = make_float4(0.f, 0.f, 0.f, 0.f);
                if (gn < N) v = *(const float4*)(B + (size_t)gn * ldb + k0 + 4 * q);
                Bs[(4 * q + 0) * BS_S + n] = f2tf32(v.x);
                Bs[(4 * q + 1) * BS_S + n] = f2tf32(v.y);
                Bs[(4 * q + 2) * BS_S + n] = f2tf32(v.z);
                Bs[(4 * q + 3) * BS_S + n] = f2tf32(v.w);
            }
        }
        __syncthreads();

        #pragma unroll
        for (int kk = 0; kk < 4; kk++) {
            const int kb = kk * 8;
            uint32_t af[2][4];
            uint32_t bf[8][2];
            #pragma unroll
            for (int mi = 0; mi < 2; mi++) {
                int r = wm * 32 + mi * 16 + gid;
                af[mi][0] = As[r * AS_S + kb + tig];
                af[mi][1] = As[(r + 8) * AS_S + kb + tig];
                af[mi][2] = As[r * AS_S + kb + tig + 4];
                af[mi][3] = As[(r + 8) * AS_S + kb + tig + 4];
            }
            #pragma unroll
            for (int ni = 0; ni < 8; ni++) {
                int c = wn * 64 + ni * 8 + gid;
                bf[ni][0] = Bs[(kb + tig) * BS_S + c];
                bf[ni][1] = Bs[(kb + tig + 4) * BS_S + c];
            }
            #pragma unroll
            for (int mi = 0; mi < 2; mi++)
                #pragma unroll
                for (int ni = 0; ni < 8; ni++)
                    mma_tf32(acc[mi][ni], af[mi], bf[ni]);
        }
        __syncthreads();
    }

    // ---- epilogue ----
    #pragma unroll
    for (int mi = 0; mi < 2; mi++) {
        int r0 = bm + wm * 32 + mi * 16 + gid;
        int r1 = r0 + 8;
        #pragma unroll
        for (int ni = 0; ni < 8; ni++) {
            int c = bn + wn * 64 + ni * 8 + tig * 2;
            float* ap = acc[mi][ni];
            if (r0 < M) {
                if (c < N) {
                    float v = ap[0]; if (ADD) v += Cadd[(size_t)r0 * ldc + c];
                    C[(size_t)r0 * ldc + c] = v;
                }
                if (c + 1 < N) {
                    float v = ap[1]; if (ADD) v += Cadd[(size_t)r0 * ldc + c + 1];
                    C[(size_t)r0 * ldc + c + 1] = v;
                }
            }
            if (r1 < M) {
                if (c < N) {
                    float v = ap[2]; if (ADD) v += Cadd[(size_t)r1 * ldc + c];
                    C[(size_t)r1 * ldc + c] = v;
                }
                if (c + 1 < N) {
                    float v = ap[3]; if (ADD) v += Cadd[(size_t)r1 * ldc + c + 1];
                    C[(size_t)r1 * ldc + c + 1] = v;
                }
            }
        }
    }
}

// ---------------- rmsnorm ----------------
__global__ void rms_kernel(const float* __restrict__ in, const float* __restrict__ w,
                           float* __restrict__ out, int D)
{
    int t = blockIdx.x;
    const float* row = in + (size_t)t * D;
    float s = 0.0f;
    for (int d = threadIdx.x; d < D; d += blockDim.x) { float v = row[d]; s += v * v; }
    s = blockReduceSum(s);
    float inv = rsqrtf(s / (float)D + EPSF);
    for (int d = threadIdx.x; d < D; d += blockDim.x)
        out[(size_t)t * D + d] = row[d] * inv * w[d];
}

// ---------------- kv gate + ape ----------------
__global__ void kvgate_kernel(const float* __restrict__ A, const float* __restrict__ Gt,
                              const float* __restrict__ ape, float* __restrict__ out, int W)
{
    int i = blockIdx.x * blockDim.x + threadIdx.x;
    if (i >= T_ * W) return;
    int t = i / W, e = i - t * W;
    float g = 1.0f / (1.0f + expf(-Gt[i]));
    out[i] = A[i] * g + ape[(t & 3) * W + e];
}

// ---------------- compress ----------------
__global__ void compress_kernel(const float* __restrict__ kvf, const float* __restrict__ w,
                                float* __restrict__ out, int d)
{
    int b = blockIdx.x;
    int e = threadIdx.x;
    int W = 2 * d;
    float m = 0.0f;
    if (b > 0) {
        #pragma unroll
        for (int r = 0; r < 4; r++) m += kvf[(size_t)((b - 1) * 4 + r) * W + e];
    }
    #pragma unroll
    for (int r = 0; r < 4; r++) m += kvf[(size_t)(b * 4 + r) * W + d + e];
    m *= 0.125f;
    float ssq = blockReduceSum(m * m);
    float inv = rsqrtf(ssq / (float)d + EPSF);
    out[(size_t)b * d + e] = m * inv * w[e];
}

// ---------------- RoPE ----------------
__global__ void rope_kernel(float* __restrict__ x, const int* __restrict__ positions,
                            int Hh, int Dd, int ropeOff, int compPos)
{
    int th = blockIdx.x;
    int t = th / Hh;
    int i = threadIdx.x;
    float* p = x + ((size_t)th) * Dd + ropeOff;
    int pos = compPos ? (4 * (t + 1) - 1) : positions[t];
    double freq = exp(-((double)(2 * i) / 64.0) * LOG_THETA);
    double ang = (double)pos * freq;
    float c = (float)cos(ang), s = (float)sin(ang);
    float x0 = p[2 * i], x1 = p[2 * i + 1];
    p[2 * i]     = x0 * c - x1 * s;
    p[2 * i + 1] = x0 * s + x1 * c;
}

// ---------------- iscore reduce ----------------
__global__ void iscore_reduce_kernel(const float* __restrict__ R, const float* __restrict__ iw,
                                     float* __restrict__ isc)
{
    int t = blockIdx.x;
    __shared__ float ws[HI_];
    if (threadIdx.x < HI_) ws[threadIdx.x] = iw[t * HI_ + threadIdx.x];
    __syncthreads();
    for (int s = threadIdx.x; s < SC_; s += blockDim.x) {
        const float* Rp = R + (size_t)t * HI_ * SC_ + s;
        float acc = 0.0f;
        #pragma unroll
        for (int h = 0; h < HI_; h++)
            acc += ws[h] * fmaxf(Rp[(size_t)h * SC_], 0.0f);
        isc[t * SC_ + s] = acc * ISCALE_;
    }
}

// ---------------- exact top-256 ----------------
__global__ void topk_kernel(const float* __restrict__ isc, int* __restrict__ selidx,
                            int* __restrict__ selcnt)
{
    int t = blockIdx.x;
    __shared__ float sv[SC_];
    __shared__ int   si[SC_];
    int tid = threadIdx.x;
    int visCount = (t >= 3) ? ((t - 3) / 4 + 1) : 0;
    for (int i = tid; i < SC_; i += 256) {
        sv[i] = (i < visCount) ? isc[t * SC_ + i] : NEGF;
        si[i] = i;
    }
    __syncthreads();
    for (int k = 2; k <= SC_; k <<= 1) {
        for (int j = k >> 1; j > 0; j >>= 1) {
            for (int base = tid; base < SC_; base += 256) {
                int partner = base ^ j;
                if (partner > base) {
                    bool up = ((base & k) == 0);
                    float va = sv[base], vb = sv[partner];
                    int ia = si[base], ib = si[partner];
                    bool aFirst = (va > vb) || (va == vb && ia < ib);
                    if (up ? !aFirst : aFirst) {
                        sv[base] = vb; sv[partner] = va;
                        si[base] = ib; si[partner] = ia;
                    }
                }
            }
            __syncthreads();
        }
    }
    int cnt = min(visCount, TOPK_);
    if (tid == 0) selcnt[t] = cnt;
    for (int r = tid; r < cnt; r += 256) selidx[t * TOPK_ + r] = si[r];
}

// ---------------- sparse attention ----------------
__global__ void attn_kernel(const float* __restrict__ q, const float* __restrict__ kvc,
                            const int* __restrict__ selidx, const int* __restrict__ selcnt,
                            const float* __restrict__ sink, float* __restrict__ o)
{
    int h = blockIdx.x, t = blockIdx.y;
    int tid = threadIdx.x;
    __shared__ float qs[DH_];
    __shared__ float pl[TOPK_];
    __shared__ int   ss[TOPK_];
    int cnt = selcnt[t];
    qs[tid] = q[((size_t)t * H_ + h) * DH_ + tid];
    if (tid < cnt) ss[tid] = selidx[t * TOPK_ + tid];
    __syncthreads();

    float lg = NEGF;
    if (tid < cnt) {
        const float4* kr = (const float4*)(kvc + (size_t)ss[tid] * DH_);
        const float4* qr = (const float4*)qs;
        float dot = 0.0f;
        #pragma unroll 16
        for (int i = 0; i < DH_ / 4; i++) {
            float4 a = qr[i], b = kr[i];
            dot += a.x * b.x + a.y * b.y + a.z * b.z + a.w * b.w;
        }
        lg = dot * SCALE_;
    }
    float m = blockReduceMax(lg);
    float snk = sink[h];
    m = fmaxf(m, snk);
    float e = (tid < cnt) ? expf(lg - m) : 0.0f;
    float denom = blockReduceSum(e) + expf(snk - m);
    if (tid < cnt) pl[tid] = e / denom;
    __syncthreads();

    float acc = 0.0f;
    for (int j = 0; j < cnt; j++)
        acc += pl[j] * kvc[(size_t)ss[j] * DH_ + tid];
    o[((size_t)t * H_ + h) * DH_ + tid] = acc;
}

// ---------------- silu ----------------
__global__ void silu_kernel(const float* __restrict__ gu, float* __restrict__ act)
{
    size_t i = (size_t)blockIdx.x * blockDim.x + threadIdx.x;
    if (i >= (size_t)T_ * II_) return;
    size_t t = i / II_, c = i - t * II_;
    float a = gu[t * (2 * II_) + c];
    float b = gu[t * (2 * II_) + II_ + c];
    act[i] = a / (1.0f + expf(-a)) * b;
}

// ---------------- host ----------------
static inline dim3 ggrid(int M, int N) { return dim3((N + BN - 1) / BN, (M + BM - 1) / BM); }

extern "C" void kernel_launch(void* const* d_in, const int* in_sizes, int n_in,
                              void* d_out, int out_size)
{
    const float* hidden      = (const float*)d_in[0];
    const int*   positions   = (const int*)  d_in[1];
    const float* ln1_w       = (const float*)d_in[2];
    const float* ln2_w       = (const float*)d_in[3];
    const float* wq_a        = (const float*)d_in[4];
    const float* q_norm_w    = (const float*)d_in[5];
    const float* wq_b        = (const float*)d_in[6];
    const float* comp_wkv    = (const float*)d_in[7];
    const float* comp_wgate  = (const float*)d_in[8];
    const float* comp_ape    = (const float*)d_in[9];
    const float* comp_norm_w = (const float*)d_in[10];
    const float* idx_wq_b    = (const float*)d_in[11];
    const float* idx_wproj   = (const float*)d_in[12];
    const float* icomp_wkv   = (const float*)d_in[13];
    const float* icomp_wgate = (const float*)d_in[14];
    const float* icomp_ape   = (const float*)d_in[15];
    const float* icomp_norm_w= (const float*)d_in[16];
    const float* attn_sink   = (const float*)d_in[17];
    const float* wo_a        = (const float*)d_in[18];
    const float* wo_b        = (const float*)d_in[19];
    const float* gate_up_w   = (const float*)d_in[20];
    const float* down_w      = (const float*)d_in[21];
    float* out = (float*)d_out;

    float *px, *pqr, *pq, *pqi, *pkvA, *pkvG, *pkvF, *pkvc;
    float *pikA, *pikG, *pikF, *pki, *piw, *pR, *pisc, *po, *poa, *ph, *px2, *pgu, *pact;
    int *pselidx, *pselcnt;
    cudaGetSymbolAddress((void**)&px,   g_x);
    cudaGetSymbolAddress((void**)&pqr,  g_qr);
    cudaGetSymbolAddress((void**)&pq,   g_q);
    cudaGetSymbolAddress((void**)&pqi,  g_qi);
    cudaGetSymbolAddress((void**)&pkvA, g_kvA);
    cudaGetSymbolAddress((void**)&pkvG, g_kvG);
    cudaGetSymbolAddress((void**)&pkvF, g_kvF);
    cudaGetSymbolAddress((void**)&pkvc, g_kvc);
    cudaGetSymbolAddress((void**)&pikA, g_ikA);
    cudaGetSymbolAddress((void**)&pikG, g_ikG);
    cudaGetSymbolAddress((void**)&pikF, g_ikF);
    cudaGetSymbolAddress((void**)&pki,  g_ki);
    cudaGetSymbolAddress((void**)&piw,  g_iw);
    cudaGetSymbolAddress((void**)&pR,   g_R);
    cudaGetSymbolAddress((void**)&pisc, g_isc);
    cudaGetSymbolAddress((void**)&pselidx, g_selidx);
    cudaGetSymbolAddress((void**)&pselcnt, g_selcnt);
    cudaGetSymbolAddress((void**)&po,   g_o);
    cudaGetSymbolAddress((void**)&poa,  g_oa);
    cudaGetSymbolAddress((void**)&ph,   g_h);
    cudaGetSymbolAddress((void**)&px2,  g_x2);
    cudaGetSymbolAddress((void**)&pgu,  g_gu);
    cudaGetSymbolAddress((void**)&pact, g_act);

    // 1) x = rms(hidden, ln1)
    rms_kernel<<<T_, 256>>>(hidden, ln1_w, px, DIM_);

    // 2) qr = rms(x @ wq_a, q_norm)
    tgemm_kernel<false,false><<<ggrid(T_, QL_), 256>>>(T_, QL_, DIM_, px, DIM_, wq_a, QL_, nullptr, pqr, QL_);
    rms_kernel<<<T_, 256>>>(pqr, q_norm_w, pqr, QL_);

    // 3) q / qi projections + rope
    tgemm_kernel<false,false><<<ggrid(T_, H_*DH_), 256>>>(T_, H_*DH_, QL_, pqr, QL_, wq_b, H_*DH_, nullptr, pq, H_*DH_);
    tgemm_kernel<false,false><<<ggrid(T_, HI_*DI_), 256>>>(T_, HI_*DI_, QL_, pqr, QL_, idx_wq_b, HI_*DI_, nullptr, pqi, HI_*DI_);
    rope_kernel<<<T_ * H_,  32>>>(pq,  positions, H_,  DH_, NOPE_,  0);
    rope_kernel<<<T_ * HI_, 32>>>(pqi, positions, HI_, DI_, INOPE_, 0);

    // 4) kvc compression + rope
    tgemm_kernel<false,false><<<ggrid(T_, 2*DH_), 256>>>(T_, 2*DH_, DIM_, px, DIM_, comp_wkv,   2*DH_, nullptr, pkvA, 2*DH_);
    tgemm_kernel<false,false><<<ggrid(T_, 2*DH_), 256>>>(T_, 2*DH_, DIM_, px, DIM_, comp_wgate, 2*DH_, nullptr, pkvG, 2*DH_);
    kvgate_kernel<<<(T_ * 2 * DH_ + 255) / 256, 256>>>(pkvA, pkvG, comp_ape, pkvF, 2*DH_);
    compress_kernel<<<SC_, DH_>>>(pkvF, comp_norm_w, pkvc, DH_);
    rope_kernel<<<SC_, 32>>>(pkvc, nullptr, 1, DH_, NOPE_, 1);

    // 5) ki compression + rope
    tgemm_kernel<false,false><<<ggrid(T_, 2*DI_), 256>>>(T_, 2*DI_, DIM_, px, DIM_, icomp_wkv,   2*DI_, nullptr, pikA, 2*DI_);
    tgemm_kernel<false,false><<<ggrid(T_, 2*DI_), 256>>>(T_, 2*DI_, DIM_, px, DIM_, icomp_wgate, 2*DI_, nullptr, pikG, 2*DI_);
    kvgate_kernel<<<(T_ * 2 * DI_ + 255) / 256, 256>>>(pikA, pikG, icomp_ape, pikF, 2*DI_);
    compress_kernel<<<SC_, DI_>>>(pikF, icomp_norm_w, pki, DI_);
    rope_kernel<<<SC_, 32>>>(pki, nullptr, 1, DI_, INOPE_, 1);

    // 6) iw
    tgemm_kernel<false,false><<<ggrid(T_, HI_), 256>>>(T_, HI_, DIM_, px, DIM_, idx_wproj, HI_, nullptr, piw, HI_);

    // 7) R = qi @ ki^T ; iscore reduce
    tgemm_kernel<true,false><<<ggrid(T_*HI_, SC_), 256>>>(T_*HI_, SC_, DI_, pqi, DI_, pki, DI_, nullptr, pR, SC_);
    iscore_reduce_kernel<<<T_, 256>>>(pR, piw, pisc);

    // 8) top-256
    topk_kernel<<<T_, 256>>>(pisc, pselidx, pselcnt);

    // 9) sparse attention
    attn_kernel<<<dim3(H_, T_), DH_>>>(pq, pkvc, pselidx, pselcnt, attn_sink, po);

    // 10) output proj
    for (int g = 0; g < G_; g++) {
        tgemm_kernel<true,false><<<ggrid(T_, OLORA_), 256>>>(
            T_, OLORA_, (H_/G_)*DH_,
            po + g * (H_/G_)*DH_, H_*DH_,
            wo_a + (size_t)g * OLORA_ * (H_/G_)*DH_, (H_/G_)*DH_,
            nullptr, poa + g * OLORA_, G_*OLORA_);
    }
    tgemm_kernel<false,true><<<ggrid(T_, DIM_), 256>>>(T_, DIM_, G_*OLORA_, poa, G_*OLORA_, wo_b, DIM_, hidden, ph, DIM_);

    // 11) MLP
    rms_kernel<<<T_, 256>>>(ph, ln2_w, px2, DIM_);
    tgemm_kernel<false,false><<<ggrid(T_, 2*II_), 256>>>(T_, 2*II_, DIM_, px2, DIM_, gate_up_w, 2*II_, nullptr, pgu, 2*II_);
    silu_kernel<<<(int)(((size_t)T_ * II_ + 255) / 256), 256>>>(pgu, pact);
    tgemm_kernel<false,true><<<ggrid(T_, DIM_), 256>>>(T_, DIM_, II_, pact, II_, down_w, DIM_, ph, out, DIM_);
}

// round 3
// speedup vs baseline: 3.3726x; 1.4481x over previous
#include <cuda_runtime.h>
#include <math.h>
#include <stdint.h>

// ---------------- problem constants ----------------
#define T_    2048
#define DIM_  2048
#define QL_   1536
#define H_    16
#define DH_   256
#define NOPE_ 192
#define HI_   32
#define DI_   128
#define INOPE_ 64
#define SC_   512
#define TOPK_ 256
#define II_   8192
#define G_    4
#define OLORA_ 512
#define EPSF  1e-6f
#define NEGF  (-1e30f)
#define SCALE_   0.0625f
#define ISCALE_  0.08838834764831845f
#define LOG_THETA 11.98292909421596506

// ---------------- scratch ----------------
__device__ float g_x   [T_ * DIM_];
__device__ float g_qr  [T_ * QL_];
__device__ float g_q   [T_ * H_ * DH_];
__device__ float g_qi  [T_ * HI_ * DI_];
__device__ float g_kvA [T_ * 2 * DH_];
__device__ float g_kvG [T_ * 2 * DH_];
__device__ float g_kvF [T_ * 2 * DH_];
__device__ float g_kvc [SC_ * DH_];
__device__ float g_ikA [T_ * 2 * DI_];
__device__ float g_ikG [T_ * 2 * DI_];
__device__ float g_ikF [T_ * 2 * DI_];
__device__ float g_ki  [SC_ * DI_];
__device__ float g_iw  [T_ * HI_];
__device__ float g_R   [(size_t)T_ * HI_ * SC_];
__device__ float g_isc [T_ * SC_];
__device__ int   g_selidx[T_ * TOPK_];
__device__ int   g_selcnt[T_];
__device__ float g_o   [T_ * H_ * DH_];
__device__ float g_oa  [T_ * G_ * OLORA_];
__device__ float g_h   [T_ * DIM_];
__device__ float g_x2  [T_ * DIM_];
__device__ float g_gu  [(size_t)T_ * 2 * II_];
__device__ float g_act [(size_t)T_ * II_];

// ---------------- reductions ----------------
__device__ __forceinline__ float blockReduceSum(float v) {
    __shared__ float sh[32];
    int lane = threadIdx.x & 31, wid = threadIdx.x >> 5;
    #pragma unroll
    for (int o = 16; o > 0; o >>= 1) v += __shfl_xor_sync(0xffffffffu, v, o);
    if (lane == 0) sh[wid] = v;
    __syncthreads();
    int nw = (blockDim.x + 31) >> 5;
    if (wid == 0) {
        float r = (lane < nw) ? sh[lane] : 0.0f;
        #pragma unroll
        for (int o = 16; o > 0; o >>= 1) r += __shfl_xor_sync(0xffffffffu, r, o);
        if (lane == 0) sh[0] = r;
    }
    __syncthreads();
    float res = sh[0];
    __syncthreads();
    return res;
}

// ---------------- tf32 / cp.async helpers ----------------
__device__ __forceinline__ uint32_t f2tf32(float x) {
    uint32_t r;
    asm("cvt.rna.tf32.f32 %0, %1;" : "=r"(r) : "f"(x));
    return r;
}

__device__ __forceinline__ void mma_tf32(float* d, const uint32_t* a, const uint32_t* b) {
    asm volatile(
        "mma.sync.aligned.m16n8k8.row.col.f32.tf32.tf32.f32 "
        "{%0,%1,%2,%3}, {%4,%5,%6,%7}, {%8,%9}, {%0,%1,%2,%3};"
        : "+f"(d[0]), "+f"(d[1]), "+f"(d[2]), "+f"(d[3])
        : "r"(a[0]), "r"(a[1]), "r"(a[2]), "r"(a[3]), "r"(b[0]), "r"(b[1]));
}

__device__ __forceinline__ void cp16(float* smem_dst, const float* gsrc, bool pred) {
    uint32_t s = (uint32_t)__cvta_generic_to_shared(smem_dst);
    int sz = pred ? 16 : 0;
    asm volatile("cp.async.cg.shared.global [%0], [%1], 16, %2;\n"
                 :: "r"(s), "l"(gsrc), "r"(sz));
}
#define CP_COMMIT() asm volatile("cp.async.commit_group;" ::: "memory")
#define CP_WAIT1()  asm volatile("cp.async.wait_group 1;" ::: "memory")
#define CP_WAIT0()  asm volatile("cp.async.wait_group 0;" ::: "memory")

// ---------------- tensor-core TF32 GEMM, 128x128x32, 8 warps ----------------
// C[M,N] = A[M,K] @ (BT ? B[N,K]^T : B[K,N]) (+ Cadd).
// Requirements: K%32==0, N%32==0 or guarded, M%128==0 assumed but guarded,
// lda/ldb%4==0.
#define BM 128
#define BN 128
#define BK 32
#define AS_S 36              // A smem: [m][k], stride 36 (frag loads conflict-free)
#define BS_S 136             // B smem: [k][n], stride 136 (frag loads conflict-free)
#define A_TILE (BM * AS_S)   // 4608 floats
#define B_TILE (BK * BS_S)   // 4352 floats
#define SMEM_PIPE_BYTES   ((A_TILE + B_TILE) * 2 * 4)   // 71680
#define SMEM_SINGLE_BYTES ((A_TILE + B_TILE) * 4)       // 35840

template<bool BT, bool ADD>
__global__ void __launch_bounds__(256, 2) tgemm_kernel(
    int M, int N, int K,
    const float* __restrict__ A, int lda,
    const float* __restrict__ B, int ldb,
    const float* __restrict__ Cadd,
    float* __restrict__ C, int ldc)
{
    extern __shared__ float smem[];
    const int bm = blockIdx.y * BM;
    const int bn = blockIdx.x * BN;
    const int tid = threadIdx.x;
    const int lane = tid & 31;
    const int wid = tid >> 5;
    const int wm = wid & 3;
    const int wn = wid >> 2;
    const int gid = lane >> 2;
    const int tig = lane & 3;

    float acc[2][8][4];
    #pragma unroll
    for (int mi = 0; mi < 2; mi++)
        #pragma unroll
        for (int ni = 0; ni < 8; ni++)
            #pragma unroll
            for (int r = 0; r < 4; r++) acc[mi][ni][r] = 0.0f;

    const int nIter = K / BK;

    // fragment compute over one ready stage
    auto frag_compute = [&](const float* sA, const float* sB) {
        #pragma unroll
        for (int kk = 0; kk < 4; kk++) {
            const int kb = kk * 8;
            uint32_t af[2][4];
            uint32_t bf[8][2];
            #pragma unroll
            for (int mi = 0; mi < 2; mi++) {
                int r = wm * 32 + mi * 16 + gid;
                af[mi][0] = f2tf32(sA[r * AS_S + kb + tig]);
                af[mi][1] = f2tf32(sA[(r + 8) * AS_S + kb + tig]);
                af[mi][2] = f2tf32(sA[r * AS_S + kb + tig + 4]);
                af[mi][3] = f2tf32(sA[(r + 8) * AS_S + kb + tig + 4]);
            }
            #pragma unroll
            for (int ni = 0; ni < 8; ni++) {
                int c = wn * 64 + ni * 8 + gid;
                bf[ni][0] = f2tf32(sB[(kb + tig) * BS_S + c]);
                bf[ni][1] = f2tf32(sB[(kb + tig + 4) * BS_S + c]);
            }
            #pragma unroll
            for (int mi = 0; mi < 2; mi++)
                #pragma unroll
                for (int ni = 0; ni < 8; ni++)
                    mma_tf32(acc[mi][ni], af[mi], bf[ni]);
        }
    };

    if (!BT) {
        // -------- pipelined path: cp.async double buffer --------
        float* sA[2] = { smem, smem + A_TILE };
        float* sB[2] = { smem + 2 * A_TILE, smem + 2 * A_TILE + B_TILE };

        auto issue = [&](int st, int k0) {
            #pragma unroll
            for (int i = 0; i < 4; i++) {
                int f = tid + i * 256;
                int r = f >> 3, q = f & 7;
                int gr = bm + r;
                cp16(&sA[st][r * AS_S + 4 * q],
                     A + (size_t)gr * lda + k0 + 4 * q, gr < M);
            }
            #pragma unroll
            for (int i = 0; i < 4; i++) {
                int f = tid + i * 256;
                int k = f >> 5, q = f & 31;
                int gc = bn + 4 * q;
                cp16(&sB[st][k * BS_S + 4 * q],
                     B + (size_t)(k0 + k) * ldb + gc, gc < N);
            }
        };

        issue(0, 0);
        CP_COMMIT();
        for (int it = 0; it < nIter; ++it) {
            if (it + 1 < nIter) {
                issue((it + 1) & 1, (it + 1) * BK);
                CP_COMMIT();
                CP_WAIT1();
            } else {
                CP_WAIT0();
            }
            __syncthreads();
            frag_compute(sA[it & 1], sB[it & 1]);
            __syncthreads();
        }
    } else {
        // -------- single-buffer sync path (transposed B; small GEMMs only) --------
        float* sA = smem;
        float* sB = smem + A_TILE;
        for (int it = 0; it < nIter; ++it) {
            int k0 = it * BK;
            #pragma unroll
            for (int i = 0; i < 4; i++) {
                int f = tid + i * 256;
                int r = f >> 3, q = f & 7;
                int gr = bm + r;
                float4 v = make_float4(0.f, 0.f, 0.f, 0.f);
                if (gr < M) v = *(const float4*)(A + (size_t)gr * lda + k0 + 4 * q);
                float* dst = &sA[r * AS_S + 4 * q];
                dst[0] = v.x; dst[1] = v.y; dst[2] = v.z; dst[3] = v.w;
            }
            #pragma unroll
            for (int i = 0; i < 4; i++) {
                int f = tid + i * 256;
                int n = f >> 3, q = f & 7;
                int gn = bn + n;
                float4 v = make_float4(0.f, 0.f, 0.f, 0.f);
                if (gn < N) v = *(const float4*)(B + (size_t)gn * ldb + k0 + 4 * q);
                sB[(4 * q + 0) * BS_S + n] = v.x;
                sB[(4 * q + 1) * BS_S + n] = v.y;
                sB[(4 * q + 2) * BS_S + n] = v.z;
                sB[(4 * q + 3) * BS_S + n] = v.w;
            }
            __syncthreads();
            frag_compute(sA, sB);
            __syncthreads();
        }
    }

    // ---- epilogue (c is even; N is a multiple of 32, so c+1<N when c<N) ----
    #pragma unroll
    for (int mi = 0; mi < 2; mi++) {
        int r0 = bm + wm * 32 + mi * 16 + gid;
        int r1 = r0 + 8;
        #pragma unroll
        for (int ni = 0; ni < 8; ni++) {
            int c = bn + wn * 64 + ni * 8 + tig * 2;
            float* ap = acc[mi][ni];
            if (c < N) {
                if (r0 < M) {
                    float2 v = make_float2(ap[0], ap[1]);
                    if (ADD) {
                        float2 a = *(const float2*)(Cadd + (size_t)r0 * ldc + c);
                        v.x += a.x; v.y += a.y;
                    }
                    *(float2*)(C + (size_t)r0 * ldc + c) = v;
                }
                if (r1 < M) {
                    float2 v = make_float2(ap[2], ap[3]);
                    if (ADD) {
                        float2 a = *(const float2*)(Cadd + (size_t)r1 * ldc + c);
                        v.x += a.x; v.y += a.y;
                    }
                    *(float2*)(C + (size_t)r1 * ldc + c) = v;
                }
            }
        }
    }
}

// ---------------- rmsnorm ----------------
__global__ void rms_kernel(const float* __restrict__ in, const float* __restrict__ w,
                           float* __restrict__ out, int D)
{
    int t = blockIdx.x;
    const float* row = in + (size_t)t * D;
    float s = 0.0f;
    for (int d = threadIdx.x; d < D; d += blockDim.x) { float v = row[d]; s += v * v; }
    s = blockReduceSum(s);
    float inv = rsqrtf(s / (float)D + EPSF);
    for (int d = threadIdx.x; d < D; d += blockDim.x)
        out[(size_t)t * D + d] = row[d] * inv * w[d];
}

// ---------------- kv gate + ape ----------------
__global__ void kvgate_kernel(const float* __restrict__ A, const float* __restrict__ Gt,
                              const float* __restrict__ ape, float* __restrict__ out, int W)
{
    int i = blockIdx.x * blockDim.x + threadIdx.x;
    if (i >= T_ * W) return;
    int t = i / W, e = i - t * W;
    float g = 1.0f / (1.0f + expf(-Gt[i]));
    out[i] = A[i] * g + ape[(t & 3) * W + e];
}

// ---------------- compress ----------------
__global__ void compress_kernel(const float* __restrict__ kvf, const float* __restrict__ w,
                                float* __restrict__ out, int d)
{
    int b = blockIdx.x;
    int e = threadIdx.x;
    int W = 2 * d;
    float m = 0.0f;
    if (b > 0) {
        #pragma unroll
        for (int r = 0; r < 4; r++) m += kvf[(size_t)((b - 1) * 4 + r) * W + e];
    }
    #pragma unroll
    for (int r = 0; r < 4; r++) m += kvf[(size_t)(b * 4 + r) * W + d + e];
    m *= 0.125f;
    float ssq = blockReduceSum(m * m);
    float inv = rsqrtf(ssq / (float)d + EPSF);
    out[(size_t)b * d + e] = m * inv * w[e];
}

// ---------------- RoPE ----------------
__global__ void rope_kernel(float* __restrict__ x, const int* __restrict__ positions,
                            int Hh, int Dd, int ropeOff, int compPos)
{
    int th = blockIdx.x;
    int t = th / Hh;
    int i = threadIdx.x;
    float* p = x + ((size_t)th) * Dd + ropeOff;
    int pos = compPos ? (4 * (t + 1) - 1) : positions[t];
    double freq = exp(-((double)(2 * i) / 64.0) * LOG_THETA);
    double ang = (double)pos * freq;
    float c = (float)cos(ang), s = (float)sin(ang);
    float x0 = p[2 * i], x1 = p[2 * i + 1];
    p[2 * i]     = x0 * c - x1 * s;
    p[2 * i + 1] = x0 * s + x1 * c;
}

// ---------------- iscore reduce ----------------
__global__ void iscore_reduce_kernel(const float* __restrict__ R, const float* __restrict__ iw,
                                     float* __restrict__ isc)
{
    int t = blockIdx.x;
    __shared__ float ws[HI_];
    if (threadIdx.x < HI_) ws[threadIdx.x] = iw[t * HI_ + threadIdx.x];
    __syncthreads();
    for (int s = threadIdx.x; s < SC_; s += blockDim.x) {
        const float* Rp = R + (size_t)t * HI_ * SC_ + s;
        float acc = 0.0f;
        #pragma unroll
        for (int h = 0; h < HI_; h++)
            acc += ws[h] * fmaxf(Rp[(size_t)h * SC_], 0.0f);
        isc[t * SC_ + s] = acc * ISCALE_;
    }
}

// ---------------- exact top-256 ----------------
__global__ void topk_kernel(const float* __restrict__ isc, int* __restrict__ selidx,
                            int* __restrict__ selcnt)
{
    int t = blockIdx.x;
    __shared__ float sv[SC_];
    __shared__ int   si[SC_];
    int tid = threadIdx.x;
    int visCount = (t >= 3) ? ((t - 3) / 4 + 1) : 0;
    for (int i = tid; i < SC_; i += 256) {
        sv[i] = (i < visCount) ? isc[t * SC_ + i] : NEGF;
        si[i] = i;
    }
    __syncthreads();
    for (int k = 2; k <= SC_; k <<= 1) {
        for (int j = k >> 1; j > 0; j >>= 1) {
            for (int base = tid; base < SC_; base += 256) {
                int partner = base ^ j;
                if (partner > base) {
                    bool up = ((base & k) == 0);
                    float va = sv[base], vb = sv[partner];
                    int ia = si[base], ib = si[partner];
                    bool aFirst = (va > vb) || (va == vb && ia < ib);
                    if (up ? !aFirst : aFirst) {
                        sv[base] = vb; sv[partner] = va;
                        si[base] = ib; si[partner] = ia;
                    }
                }
            }
            __syncthreads();
        }
    }
    int cnt = min(visCount, TOPK_);
    if (tid == 0) selcnt[t] = cnt;
    for (int r = tid; r < cnt; r += 256) selidx[t * TOPK_ + r] = si[r];
}

// ---------------- head-shared flash attention (block per token, warp per head) ----------------
__global__ void __launch_bounds__(512) attn2_kernel(
    const float* __restrict__ q, const float* __restrict__ kvc,
    const int* __restrict__ selidx, const int* __restrict__ selcnt,
    const float* __restrict__ sink, float* __restrict__ o)
{
    __shared__ float kt[32][DH_];    // 32 KB tile of selected K rows
    __shared__ int   ss[TOPK_];
    int t = blockIdx.x;
    int tid = threadIdx.x, lane = tid & 31, w = tid >> 5;   // w = head 0..15
    int cnt = selcnt[t];
    for (int i = tid; i < cnt; i += 512) ss[i] = selidx[t * TOPK_ + i];
    __syncthreads();

    float q8[8];
    const float* qp = q + ((size_t)t * H_ + w) * DH_;
    #pragma unroll
    for (int i = 0; i < 8; i++) q8[i] = qp[lane + 32 * i];

    float m = NEGF, se = 0.0f;
    float acc[8] = {};

    for (int j0 = 0; j0 < cnt; j0 += 32) {
        int rem = min(32, cnt - j0);
        __syncthreads();   // previous tile fully consumed
        for (int f = tid; f < 32 * 64; f += 512) {
            int r = f >> 6, c4 = f & 63;
            float4 v = make_float4(0.f, 0.f, 0.f, 0.f);
            if (r < rem) v = *(const float4*)(kvc + (size_t)ss[j0 + r] * DH_ + 4 * c4);
            *(float4*)&kt[r][4 * c4] = v;
        }
        __syncthreads();
        for (int j = 0; j < rem; j++) {
            float dot = 0.0f;
            #pragma unroll
            for (int i = 0; i < 8; i++) dot += q8[i] * kt[j][lane + 32 * i];
            #pragma unroll
            for (int off = 16; off > 0; off >>= 1)
                dot += __shfl_xor_sync(0xffffffffu, dot, off);
            float lg = dot * SCALE_;
            float mn = fmaxf(m, lg);
            float sc = expf(m - mn);       // m == NEGF -> 0 (finite - finite)
            float p  = expf(lg - mn);
            se = se * sc + p;
            #pragma unroll
            for (int i = 0; i < 8; i++)
                acc[i] = acc[i] * sc + p * kt[j][lane + 32 * i];
            m = mn;
        }
    }

    float snk = sink[w];
    float mn = fmaxf(m, snk);
    float sc = expf(m - mn);   // cnt==0: m=NEGF, mn=snk -> sc=0, acc=0
    se = se * sc + expf(snk - mn);
    float inv = 1.0f / se;
    float* op = o + ((size_t)t * H_ + w) * DH_;
    #pragma unroll
    for (int i = 0; i < 8; i++) op[lane + 32 * i] = acc[i] * sc * inv;
}

// ---------------- silu ----------------
__global__ void silu_kernel(const float* __restrict__ gu, float* __restrict__ act)
{
    size_t i = (size_t)blockIdx.x * blockDim.x + threadIdx.x;
    if (i >= (size_t)T_ * II_) return;
    size_t t = i / II_, c = i - t * II_;
    float a = gu[t * (2 * II_) + c];
    float b = gu[t * (2 * II_) + II_ + c];
    act[i] = a / (1.0f + expf(-a)) * b;
}

// ---------------- host ----------------
static inline dim3 ggrid(int M, int N) { return dim3((N + BN - 1) / BN, (M + BM - 1) / BM); }

extern "C" void kernel_launch(void* const* d_in, const int* in_sizes, int n_in,
                              void* d_out, int out_size)
{
    const float* hidden      = (const float*)d_in[0];
    const int*   positions   = (const int*)  d_in[1];
    const float* ln1_w       = (const float*)d_in[2];
    const float* ln2_w       = (const float*)d_in[3];
    const float* wq_a        = (const float*)d_in[4];
    const float* q_norm_w    = (const float*)d_in[5];
    const float* wq_b        = (const float*)d_in[6];
    const float* comp_wkv    = (const float*)d_in[7];
    const float* comp_wgate  = (const float*)d_in[8];
    const float* comp_ape    = (const float*)d_in[9];
    const float* comp_norm_w = (const float*)d_in[10];
    const float* idx_wq_b    = (const float*)d_in[11];
    const float* idx_wproj   = (const float*)d_in[12];
    const float* icomp_wkv   = (const float*)d_in[13];
    const float* icomp_wgate = (const float*)d_in[14];
    const float* icomp_ape   = (const float*)d_in[15];
    const float* icomp_norm_w= (const float*)d_in[16];
    const float* attn_sink   = (const float*)d_in[17];
    const float* wo_a        = (const float*)d_in[18];
    const float* wo_b        = (const float*)d_in[19];
    const float* gate_up_w   = (const float*)d_in[20];
    const float* down_w      = (const float*)d_in[21];
    float* out = (float*)d_out;

    float *px, *pqr, *pq, *pqi, *pkvA, *pkvG, *pkvF, *pkvc;
    float *pikA, *pikG, *pikF, *pki, *piw, *pR, *pisc, *po, *poa, *ph, *px2, *pgu, *pact;
    int *pselidx, *pselcnt;
    cudaGetSymbolAddress((void**)&px,   g_x);
    cudaGetSymbolAddress((void**)&pqr,  g_qr);
    cudaGetSymbolAddress((void**)&pq,   g_q);
    cudaGetSymbolAddress((void**)&pqi,  g_qi);
    cudaGetSymbolAddress((void**)&pkvA, g_kvA);
    cudaGetSymbolAddress((void**)&pkvG, g_kvG);
    cudaGetSymbolAddress((void**)&pkvF, g_kvF);
    cudaGetSymbolAddress((void**)&pkvc, g_kvc);
    cudaGetSymbolAddress((void**)&pikA, g_ikA);
    cudaGetSymbolAddress((void**)&pikG, g_ikG);
    cudaGetSymbolAddress((void**)&pikF, g_ikF);
    cudaGetSymbolAddress((void**)&pki,  g_ki);
    cudaGetSymbolAddress((void**)&piw,  g_iw);
    cudaGetSymbolAddress((void**)&pR,   g_R);
    cudaGetSymbolAddress((void**)&pisc, g_isc);
    cudaGetSymbolAddress((void**)&pselidx, g_selidx);
    cudaGetSymbolAddress((void**)&pselcnt, g_selcnt);
    cudaGetSymbolAddress((void**)&po,   g_o);
    cudaGetSymbolAddress((void**)&poa,  g_oa);
    cudaGetSymbolAddress((void**)&ph,   g_h);
    cudaGetSymbolAddress((void**)&px2,  g_x2);
    cudaGetSymbolAddress((void**)&pgu,  g_gu);
    cudaGetSymbolAddress((void**)&pact, g_act);

    // dynamic smem opt-in (idempotent; >48KB needs the attribute)
    cudaFuncSetAttribute(tgemm_kernel<false,false>,
                         cudaFuncAttributeMaxDynamicSharedMemorySize, SMEM_PIPE_BYTES);
    cudaFuncSetAttribute(tgemm_kernel<false,true>,
                         cudaFuncAttributeMaxDynamicSharedMemorySize, SMEM_PIPE_BYTES);

    // 1) x = rms(hidden, ln1)
    rms_kernel<<<T_, 256>>>(hidden, ln1_w, px, DIM_);

    // 2) qr = rms(x @ wq_a, q_norm)
    tgemm_kernel<false,false><<<ggrid(T_, QL_), 256, SMEM_PIPE_BYTES>>>(T_, QL_, DIM_, px, DIM_, wq_a, QL_, nullptr, pqr, QL_);
    rms_kernel<<<T_, 256>>>(pqr, q_norm_w, pqr, QL_);

    // 3) q / qi projections + rope
    tgemm_kernel<false,false><<<ggrid(T_, H_*DH_), 256, SMEM_PIPE_BYTES>>>(T_, H_*DH_, QL_, pqr, QL_, wq_b, H_*DH_, nullptr, pq, H_*DH_);
    tgemm_kernel<false,false><<<ggrid(T_, HI_*DI_), 256, SMEM_PIPE_BYTES>>>(T_, HI_*DI_, QL_, pqr, QL_, idx_wq_b, HI_*DI_, nullptr, pqi, HI_*DI_);
    rope_kernel<<<T_ * H_,  32>>>(pq,  positions, H_,  DH_, NOPE_,  0);
    rope_kernel<<<T_ * HI_, 32>>>(pqi, positions, HI_, DI_, INOPE_, 0);

    // 4) kvc compression + rope
    tgemm_kernel<false,false><<<ggrid(T_, 2*DH_), 256, SMEM_PIPE_BYTES>>>(T_, 2*DH_, DIM_, px, DIM_, comp_wkv,   2*DH_, nullptr, pkvA, 2*DH_);
    tgemm_kernel<false,false><<<ggrid(T_, 2*DH_), 256, SMEM_PIPE_BYTES>>>(T_, 2*DH_, DIM_, px, DIM_, comp_wgate, 2*DH_, nullptr, pkvG, 2*DH_);
    kvgate_kernel<<<(T_ * 2 * DH_ + 255) / 256, 256>>>(pkvA, pkvG, comp_ape, pkvF, 2*DH_);
    compress_kernel<<<SC_, DH_>>>(pkvF, comp_norm_w, pkvc, DH_);
    rope_kernel<<<SC_, 32>>>(pkvc, nullptr, 1, DH_, NOPE_, 1);

    // 5) ki compression + rope
    tgemm_kernel<false,false><<<ggrid(T_, 2*DI_), 256, SMEM_PIPE_BYTES>>>(T_, 2*DI_, DIM_, px, DIM_, icomp_wkv,   2*DI_, nullptr, pikA, 2*DI_);
    tgemm_kernel<false,false><<<ggrid(T_, 2*DI_), 256, SMEM_PIPE_BYTES>>>(T_, 2*DI_, DIM_, px, DIM_, icomp_wgate, 2*DI_, nullptr, pikG, 2*DI_);
    kvgate_kernel<<<(T_ * 2 * DI_ + 255) / 256, 256>>>(pikA, pikG, icomp_ape, pikF, 2*DI_);
    compress_kernel<<<SC_, DI_>>>(pikF, icomp_norm_w, pki, DI_);
    rope_kernel<<<SC_, 32>>>(pki, nullptr, 1, DI_, INOPE_, 1);

    // 6) iw
    tgemm_kernel<false,false><<<ggrid(T_, HI_), 256, SMEM_PIPE_BYTES>>>(T_, HI_, DIM_, px, DIM_, idx_wproj, HI_, nullptr, piw, HI_);

    // 7) R = qi @ ki^T ; iscore reduce
    tgemm_kernel<true,false><<<ggrid(T_*HI_, SC_), 256, SMEM_SINGLE_BYTES>>>(T_*HI_, SC_, DI_, pqi, DI_, pki, DI_, nullptr, pR, SC_);
    iscore_reduce_kernel<<<T_, 256>>>(pR, piw, pisc);

    // 8) top-256
    topk_kernel<<<T_, 256>>>(pisc, pselidx, pselcnt);

    // 9) head-shared flash attention
    attn2_kernel<<<T_, 512>>>(pq, pkvc, pselidx, pselcnt, attn_sink, po);

    // 10) output proj
    for (int g = 0; g < G_; g++) {
        tgemm_kernel<true,false><<<ggrid(T_, OLORA_), 256, SMEM_SINGLE_BYTES>>>(
            T_, OLORA_, (H_/G_)*DH_,
            po + g * (H_/G_)*DH_, H_*DH_,
            wo_a + (size_t)g * OLORA_ * (H_/G_)*DH_, (H_/G_)*DH_,
            nullptr, poa + g * OLORA_, G_*OLORA_);
    }
    tgemm_kernel<false,true><<<ggrid(T_, DIM_), 256, SMEM_PIPE_BYTES>>>(T_, DIM_, G_*OLORA_, poa, G_*OLORA_, wo_b, DIM_, hidden, ph, DIM_);

    // 11) MLP
    rms_kernel<<<T_, 256>>>(ph, ln2_w, px2, DIM_);
    tgemm_kernel<false,false><<<ggrid(T_, 2*II_), 256, SMEM_PIPE_BYTES>>>(T_, 2*II_, DIM_, px2, DIM_, gate_up_w, 2*II_, nullptr, pgu, 2*II_);
    silu_kernel<<<(int)(((size_t)T_ * II_ + 255) / 256), 256>>>(pgu, pact);
    tgemm_kernel<false,true><<<ggrid(T_, DIM_), 256, SMEM_PIPE_BYTES>>>(T_, DIM_, II_, pact, II_, down_w, DIM_, ph, out, DIM_);
}

// round 4
// speedup vs baseline: 3.8660x; 1.1463x over previous
#include <cuda_runtime.h>
#include <math.h>
#include <stdint.h>

// ---------------- problem constants ----------------
#define T_    2048
#define DIM_  2048
#define QL_   1536
#define H_    16
#define DH_   256
#define NOPE_ 192
#define HI_   32
#define DI_   128
#define INOPE_ 64
#define SC_   512
#define TOPK_ 256
#define II_   8192
#define G_    4
#define OLORA_ 512
#define FG_   1024          // (H_/G_)*DH_
#define EPSF  1e-6f
#define NEGF  (-1e30f)
#define SCALE_   0.0625f
#define ISCALE_  0.08838834764831845f
#define LOG_THETA 11.98292909421596506

// ---------------- scratch ----------------
__device__ float g_x   [T_ * DIM_];
__device__ float g_qr  [T_ * QL_];
__device__ float g_q   [T_ * H_ * DH_];
__device__ float g_qi  [T_ * HI_ * DI_];
__device__ float g_kvA [T_ * 2 * DH_];
__device__ float g_kvG [T_ * 2 * DH_];
__device__ float g_kvF [T_ * 2 * DH_];
__device__ float g_kvc [SC_ * DH_];
__device__ float g_ikA [T_ * 2 * DI_];
__device__ float g_ikG [T_ * 2 * DI_];
__device__ float g_ikF [T_ * 2 * DI_];
__device__ float g_ki  [SC_ * DI_];
__device__ float g_kiT [DI_ * SC_];
__device__ float g_woaT[G_ * FG_ * OLORA_];
__device__ float g_iw  [T_ * HI_];
__device__ float g_R   [(size_t)T_ * HI_ * SC_];
__device__ float g_isc [T_ * SC_];
__device__ int   g_selidx[T_ * TOPK_];
__device__ int   g_selcnt[T_];
__device__ float g_o   [T_ * H_ * DH_];
__device__ float g_oa  [T_ * G_ * OLORA_];
__device__ float g_h   [T_ * DIM_];
__device__ float g_x2  [T_ * DIM_];
__device__ float g_gu  [(size_t)T_ * 2 * II_];
__device__ float g_act [(size_t)T_ * II_];
__device__ float g_ropeC[T_ * 32];
__device__ float g_ropeS[T_ * 32];

// ---------------- reductions ----------------
__device__ __forceinline__ float blockReduceSum(float v) {
    __shared__ float sh[32];
    int lane = threadIdx.x & 31, wid = threadIdx.x >> 5;
    #pragma unroll
    for (int o = 16; o > 0; o >>= 1) v += __shfl_xor_sync(0xffffffffu, v, o);
    if (lane == 0) sh[wid] = v;
    __syncthreads();
    int nw = (blockDim.x + 31) >> 5;
    if (wid == 0) {
        float r = (lane < nw) ? sh[lane] : 0.0f;
        #pragma unroll
        for (int o = 16; o > 0; o >>= 1) r += __shfl_xor_sync(0xffffffffu, r, o);
        if (lane == 0) sh[0] = r;
    }
    __syncthreads();
    float res = sh[0];
    __syncthreads();
    return res;
}

// ---------------- tf32 / cp.async helpers ----------------
__device__ __forceinline__ uint32_t f2tf32(float x) {
    uint32_t r;
    asm("cvt.rna.tf32.f32 %0, %1;" : "=r"(r) : "f"(x));
    return r;
}

__device__ __forceinline__ void mma_tf32(float* d, const uint32_t* a, const uint32_t* b) {
    asm volatile(
        "mma.sync.aligned.m16n8k8.row.col.f32.tf32.tf32.f32 "
        "{%0,%1,%2,%3}, {%4,%5,%6,%7}, {%8,%9}, {%0,%1,%2,%3};"
        : "+f"(d[0]), "+f"(d[1]), "+f"(d[2]), "+f"(d[3])
        : "r"(a[0]), "r"(a[1]), "r"(a[2]), "r"(a[3]), "r"(b[0]), "r"(b[1]));
}

__device__ __forceinline__ void cp16(float* smem_dst, const float* gsrc, bool pred) {
    uint32_t s = (uint32_t)__cvta_generic_to_shared(smem_dst);
    int sz = pred ? 16 : 0;
    asm volatile("cp.async.cg.shared.global [%0], [%1], 16, %2;\n"
                 :: "r"(s), "l"(gsrc), "r"(sz));
}
#define CP_COMMIT() asm volatile("cp.async.commit_group;" ::: "memory")
#define CP_WAIT1()  asm volatile("cp.async.wait_group 1;" ::: "memory")
#define CP_WAIT0()  asm volatile("cp.async.wait_group 0;" ::: "memory")

// ---------------- tensor-core TF32 GEMM, 128x128x32, 3-stage pipeline ----------------
// C[M,N] = A[M,K] @ B[K,N] (+ Cadd). K%32==0, N%4==0 (guard on N), lda/ldb%4==0.
#define BM 128
#define BN 128
#define BK 32
#define AS_S 36
#define BS_S 136
#define A_TILE (BM * AS_S)   // 4608 floats
#define B_TILE (BK * BS_S)   // 4352 floats
#define STAGE_F (A_TILE + B_TILE)
#define SMEM_PIPE_BYTES (STAGE_F * 3 * 4)   // 107520

template<bool ADD>
__global__ void __launch_bounds__(256, 2) tgemm_kernel(
    int M, int N, int K,
    const float* __restrict__ A, int lda,
    const float* __restrict__ B, int ldb,
    const float* __restrict__ Cadd,
    float* __restrict__ C, int ldc)
{
    extern __shared__ float smem[];
    const int bm = blockIdx.y * BM;
    const int bn = blockIdx.x * BN;
    const int tid = threadIdx.x;
    const int lane = tid & 31;
    const int wid = tid >> 5;
    const int wm = wid & 3;
    const int wn = wid >> 2;
    const int gid = lane >> 2;
    const int tig = lane & 3;

    float acc[2][8][4];
    #pragma unroll
    for (int mi = 0; mi < 2; mi++)
        #pragma unroll
        for (int ni = 0; ni < 8; ni++)
            #pragma unroll
            for (int r = 0; r < 4; r++) acc[mi][ni][r] = 0.0f;

    const int nIter = K / BK;

    auto issue = [&](int st, int k0) {
        float* sA = smem + st * STAGE_F;
        float* sB = sA + A_TILE;
        #pragma unroll
        for (int i = 0; i < 4; i++) {
            int f = tid + i * 256;
            int r = f >> 3, q = f & 7;
            int gr = bm + r;
            cp16(&sA[r * AS_S + 4 * q], A + (size_t)gr * lda + k0 + 4 * q, gr < M);
        }
        #pragma unroll
        for (int i = 0; i < 4; i++) {
            int f = tid + i * 256;
            int k = f >> 5, q = f & 31;
            int gc = bn + 4 * q;
            cp16(&sB[k * BS_S + 4 * q], B + (size_t)(k0 + k) * ldb + gc, gc < N);
        }
    };

    auto frag_compute = [&](int st) {
        const float* sA = smem + st * STAGE_F;
        const float* sB = sA + A_TILE;
        #pragma unroll
        for (int kk = 0; kk < 4; kk++) {
            const int kb = kk * 8;
            uint32_t af[2][4];
            uint32_t bf[8][2];
            #pragma unroll
            for (int mi = 0; mi < 2; mi++) {
                int r = wm * 32 + mi * 16 + gid;
                af[mi][0] = f2tf32(sA[r * AS_S + kb + tig]);
                af[mi][1] = f2tf32(sA[(r + 8) * AS_S + kb + tig]);
                af[mi][2] = f2tf32(sA[r * AS_S + kb + tig + 4]);
                af[mi][3] = f2tf32(sA[(r + 8) * AS_S + kb + tig + 4]);
            }
            #pragma unroll
            for (int ni = 0; ni < 8; ni++) {
                int c = wn * 64 + ni * 8 + gid;
                bf[ni][0] = f2tf32(sB[(kb + tig) * BS_S + c]);
                bf[ni][1] = f2tf32(sB[(kb + tig + 4) * BS_S + c]);
            }
            #pragma unroll
            for (int mi = 0; mi < 2; mi++)
                #pragma unroll
                for (int ni = 0; ni < 8; ni++)
                    mma_tf32(acc[mi][ni], af[mi], bf[ni]);
        }
    };

    // prologue: 2 stages in flight
    issue(0, 0);
    CP_COMMIT();
    if (nIter > 1) { issue(1, BK); CP_COMMIT(); }

    int st = 0;
    for (int it = 0; it < nIter; ++it) {
        if (it + 1 < nIter) CP_WAIT1(); else CP_WAIT0();
        __syncthreads();
        if (it + 2 < nIter) {
            // stage (it+2)%3 == (it-1)%3: all warps finished computing it-1 (pre-sync)
            int st2 = st + 2; if (st2 >= 3) st2 -= 3;
            issue(st2, (it + 2) * BK);
            CP_COMMIT();
        }
        frag_compute(st);
        if (++st == 3) st = 0;
    }

    // ---- epilogue ----
    #pragma unroll
    for (int mi = 0; mi < 2; mi++) {
        int r0 = bm + wm * 32 + mi * 16 + gid;
        int r1 = r0 + 8;
        #pragma unroll
        for (int ni = 0; ni < 8; ni++) {
            int c = bn + wn * 64 + ni * 8 + tig * 2;
            float* ap = acc[mi][ni];
            if (c < N) {
                if (r0 < M) {
                    float2 v = make_float2(ap[0], ap[1]);
                    if (ADD) {
                        float2 a = *(const float2*)(Cadd + (size_t)r0 * ldc + c);
                        v.x += a.x; v.y += a.y;
                    }
                    *(float2*)(C + (size_t)r0 * ldc + c) = v;
                }
                if (r1 < M) {
                    float2 v = make_float2(ap[2], ap[3]);
                    if (ADD) {
                        float2 a = *(const float2*)(Cadd + (size_t)r1 * ldc + c);
                        v.x += a.x; v.y += a.y;
                    }
                    *(float2*)(C + (size_t)r1 * ldc + c) = v;
                }
            }
        }
    }
}

// ---------------- tiled transpose: out[c][r] = in[r][c], in is R x C ----------------
__global__ void transpose_kernel(const float* __restrict__ in, float* __restrict__ out,
                                 int R, int C)
{
    __shared__ float tile[32][33];
    const float* inz = in + (size_t)blockIdx.z * R * C;
    float* outz = out + (size_t)blockIdx.z * R * C;
    int bx = blockIdx.x * 32, by = blockIdx.y * 32;
    int x = bx + threadIdx.x;
    #pragma unroll
    for (int i = 0; i < 4; i++) {
        int y = by + threadIdx.y + 8 * i;
        if (y < R && x < C) tile[threadIdx.y + 8 * i][threadIdx.x] = inz[(size_t)y * C + x];
    }
    __syncthreads();
    int x2 = by + threadIdx.x;
    #pragma unroll
    for (int i = 0; i < 4; i++) {
        int y2 = bx + threadIdx.y + 8 * i;
        if (y2 < C && x2 < R) outz[(size_t)y2 * R + x2] = tile[threadIdx.x][threadIdx.y + 8 * i];
    }
}

// ---------------- rmsnorm ----------------
__global__ void rms_kernel(const float* __restrict__ in, const float* __restrict__ w,
                           float* __restrict__ out, int D)
{
    int t = blockIdx.x;
    const float* row = in + (size_t)t * D;
    float s = 0.0f;
    for (int d = threadIdx.x; d < D; d += blockDim.x) { float v = row[d]; s += v * v; }
    s = blockReduceSum(s);
    float inv = rsqrtf(s / (float)D + EPSF);
    for (int d = threadIdx.x; d < D; d += blockDim.x)
        out[(size_t)t * D + d] = row[d] * inv * w[d];
}

// ---------------- kv gate + ape ----------------
__global__ void kvgate_kernel(const float* __restrict__ A, const float* __restrict__ Gt,
                              const float* __restrict__ ape, float* __restrict__ out, int W)
{
    int i = blockIdx.x * blockDim.x + threadIdx.x;
    if (i >= T_ * W) return;
    int t = i / W, e = i - t * W;
    float g = 1.0f / (1.0f + expf(-Gt[i]));
    out[i] = A[i] * g + ape[(t & 3) * W + e];
}

// ---------------- compress ----------------
__global__ void compress_kernel(const float* __restrict__ kvf, const float* __restrict__ w,
                                float* __restrict__ out, int d)
{
    int b = blockIdx.x;
    int e = threadIdx.x;
    int W = 2 * d;
    float m = 0.0f;
    if (b > 0) {
        #pragma unroll
        for (int r = 0; r < 4; r++) m += kvf[(size_t)((b - 1) * 4 + r) * W + e];
    }
    #pragma unroll
    for (int r = 0; r < 4; r++) m += kvf[(size_t)(b * 4 + r) * W + d + e];
    m *= 0.125f;
    float ssq = blockReduceSum(m * m);
    float inv = rsqrtf(ssq / (float)d + EPSF);
    out[(size_t)b * d + e] = m * inv * w[e];
}

// ---------------- RoPE table (fp64 trig, computed once per launch) ----------------
__global__ void rope_table_kernel(float* __restrict__ tc, float* __restrict__ ts)
{
    int i = blockIdx.x * blockDim.x + threadIdx.x;
    if (i >= T_ * 32) return;
    int pos = i >> 5, f = i & 31;
    double freq = exp(-((double)(2 * f) / 64.0) * LOG_THETA);
    double ang = (double)pos * freq;
    tc[i] = (float)cos(ang);
    ts[i] = (float)sin(ang);
}

// ---------------- RoPE apply (warp per row, table lookup) ----------------
__global__ void rope_apply_kernel(float* __restrict__ x, const int* __restrict__ positions,
                                  const float* __restrict__ tc, const float* __restrict__ ts,
                                  int Hh, int Dd, int ropeOff, int compPos, int nRows)
{
    int row = blockIdx.x * 8 + (threadIdx.x >> 5);
    if (row >= nRows) return;
    int lane = threadIdx.x & 31;
    int t = row / Hh;
    int pos = compPos ? (4 * (t + 1) - 1) : positions[t];
    float c = tc[pos * 32 + lane], s = ts[pos * 32 + lane];
    float* p = x + (size_t)row * Dd + ropeOff;
    float x0 = p[2 * lane], x1 = p[2 * lane + 1];
    p[2 * lane]     = x0 * c - x1 * s;
    p[2 * lane + 1] = x0 * s + x1 * c;
}

// ---------------- iscore reduce ----------------
__global__ void iscore_reduce_kernel(const float* __restrict__ R, const float* __restrict__ iw,
                                     float* __restrict__ isc)
{
    int t = blockIdx.x;
    __shared__ float ws[HI_];
    if (threadIdx.x < HI_) ws[threadIdx.x] = iw[t * HI_ + threadIdx.x];
    __syncthreads();
    for (int s = threadIdx.x; s < SC_; s += blockDim.x) {
        const float* Rp = R + (size_t)t * HI_ * SC_ + s;
        float acc = 0.0f;
        #pragma unroll
        for (int h = 0; h < HI_; h++)
            acc += ws[h] * fmaxf(Rp[(size_t)h * SC_], 0.0f);
        isc[t * SC_ + s] = acc * ISCALE_;
    }
}

// ---------------- exact top-256 ----------------
__global__ void topk_kernel(const float* __restrict__ isc, int* __restrict__ selidx,
                            int* __restrict__ selcnt)
{
    int t = blockIdx.x;
    __shared__ float sv[SC_];
    __shared__ int   si[SC_];
    int tid = threadIdx.x;
    int visCount = (t >= 3) ? ((t - 3) / 4 + 1) : 0;
    for (int i = tid; i < SC_; i += 256) {
        sv[i] = (i < visCount) ? isc[t * SC_ + i] : NEGF;
        si[i] = i;
    }
    __syncthreads();
    for (int k = 2; k <= SC_; k <<= 1) {
        for (int j = k >> 1; j > 0; j >>= 1) {
            for (int base = tid; base < SC_; base += 256) {
                int partner = base ^ j;
                if (partner > base) {
                    bool up = ((base & k) == 0);
                    float va = sv[base], vb = sv[partner];
                    int ia = si[base], ib = si[partner];
                    bool aFirst = (va > vb) || (va == vb && ia < ib);
                    if (up ? !aFirst : aFirst) {
                        sv[base] = vb; sv[partner] = va;
                        si[base] = ib; si[partner] = ia;
                    }
                }
            }
            __syncthreads();
        }
    }
    int cnt = min(visCount, TOPK_);
    if (tid == 0) selcnt[t] = cnt;
    for (int r = tid; r < cnt; r += 256) selidx[t * TOPK_ + r] = si[r];
}

// ---------------- head-shared flash attention ----------------
__global__ void __launch_bounds__(512) attn2_kernel(
    const float* __restrict__ q, const float* __restrict__ kvc,
    const int* __restrict__ selidx, const int* __restrict__ selcnt,
    const float* __restrict__ sink, float* __restrict__ o)
{
    __shared__ float kt[32][DH_];
    __shared__ int   ss[TOPK_];
    int t = blockIdx.x;
    int tid = threadIdx.x, lane = tid & 31, w = tid >> 5;
    int cnt = selcnt[t];
    for (int i = tid; i < cnt; i += 512) ss[i] = selidx[t * TOPK_ + i];
    __syncthreads();

    float q8[8];
    const float* qp = q + ((size_t)t * H_ + w) * DH_;
    #pragma unroll
    for (int i = 0; i < 8; i++) q8[i] = qp[lane + 32 * i];

    float m = NEGF, se = 0.0f;
    float acc[8] = {};

    for (int j0 = 0; j0 < cnt; j0 += 32) {
        int rem = min(32, cnt - j0);
        __syncthreads();
        for (int f = tid; f < 32 * 64; f += 512) {
            int r = f >> 6, c4 = f & 63;
            float4 v = make_float4(0.f, 0.f, 0.f, 0.f);
            if (r < rem) v = *(const float4*)(kvc + (size_t)ss[j0 + r] * DH_ + 4 * c4);
            *(float4*)&kt[r][4 * c4] = v;
        }
        __syncthreads();
        for (int j = 0; j < rem; j++) {
            float dot = 0.0f;
            #pragma unroll
            for (int i = 0; i < 8; i++) dot += q8[i] * kt[j][lane + 32 * i];
            #pragma unroll
            for (int off = 16; off > 0; off >>= 1)
                dot += __shfl_xor_sync(0xffffffffu, dot, off);
            float lg = dot * SCALE_;
            float mn = fmaxf(m, lg);
            float sc = expf(m - mn);
            float p  = expf(lg - mn);
            se = se * sc + p;
            #pragma unroll
            for (int i = 0; i < 8; i++)
                acc[i] = acc[i] * sc + p * kt[j][lane + 32 * i];
            m = mn;
        }
    }

    float snk = sink[w];
    float mn = fmaxf(m, snk);
    float sc = expf(m - mn);
    se = se * sc + expf(snk - mn);
    float inv = 1.0f / se;
    float* op = o + ((size_t)t * H_ + w) * DH_;
    #pragma unroll
    for (int i = 0; i < 8; i++) op[lane + 32 * i] = acc[i] * sc * inv;
}

// ---------------- silu ----------------
__global__ void silu_kernel(const float* __restrict__ gu, float* __restrict__ act)
{
    size_t i = (size_t)blockIdx.x * blockDim.x + threadIdx.x;
    if (i >= (size_t)T_ * II_) return;
    size_t t = i / II_, c = i - t * II_;
    float a = gu[t * (2 * II_) + c];
    float b = gu[t * (2 * II_) + II_ + c];
    act[i] = a / (1.0f + expf(-a)) * b;
}

// ---------------- host ----------------
static inline dim3 ggrid(int M, int N) { return dim3((N + BN - 1) / BN, (M + BM - 1) / BM); }

extern "C" void kernel_launch(void* const* d_in, const int* in_sizes, int n_in,
                              void* d_out, int out_size)
{
    const float* hidden      = (const float*)d_in[0];
    const int*   positions   = (const int*)  d_in[1];
    const float* ln1_w       = (const float*)d_in[2];
    const float* ln2_w       = (const float*)d_in[3];
    const float* wq_a        = (const float*)d_in[4];
    const float* q_norm_w    = (const float*)d_in[5];
    const float* wq_b        = (const float*)d_in[6];
    const float* comp_wkv    = (const float*)d_in[7];
    const float* comp_wgate  = (const float*)d_in[8];
    const float* comp_ape    = (const float*)d_in[9];
    const float* comp_norm_w = (const float*)d_in[10];
    const float* idx_wq_b    = (const float*)d_in[11];
    const float* idx_wproj   = (const float*)d_in[12];
    const float* icomp_wkv   = (const float*)d_in[13];
    const float* icomp_wgate = (const float*)d_in[14];
    const float* icomp_ape   = (const float*)d_in[15];
    const float* icomp_norm_w= (const float*)d_in[16];
    const float* attn_sink   = (const float*)d_in[17];
    const float* wo_a        = (const float*)d_in[18];
    const float* wo_b        = (const float*)d_in[19];
    const float* gate_up_w   = (const float*)d_in[20];
    const float* down_w      = (const float*)d_in[21];
    float* out = (float*)d_out;

    float *px, *pqr, *pq, *pqi, *pkvA, *pkvG, *pkvF, *pkvc;
    float *pikA, *pikG, *pikF, *pki, *pkiT, *pwoaT, *piw, *pR, *pisc, *po, *poa, *ph, *px2, *pgu, *pact;
    float *pRC, *pRS;
    int *pselidx, *pselcnt;
    cudaGetSymbolAddress((void**)&px,   g_x);
    cudaGetSymbolAddress((void**)&pqr,  g_qr);
    cudaGetSymbolAddress((void**)&pq,   g_q);
    cudaGetSymbolAddress((void**)&pqi,  g_qi);
    cudaGetSymbolAddress((void**)&pkvA, g_kvA);
    cudaGetSymbolAddress((void**)&pkvG, g_kvG);
    cudaGetSymbolAddress((void**)&pkvF, g_kvF);
    cudaGetSymbolAddress((void**)&pkvc, g_kvc);
    cudaGetSymbolAddress((void**)&pikA, g_ikA);
    cudaGetSymbolAddress((void**)&pikG, g_ikG);
    cudaGetSymbolAddress((void**)&pikF, g_ikF);
    cudaGetSymbolAddress((void**)&pki,  g_ki);
    cudaGetSymbolAddress((void**)&pkiT, g_kiT);
    cudaGetSymbolAddress((void**)&pwoaT,g_woaT);
    cudaGetSymbolAddress((void**)&piw,  g_iw);
    cudaGetSymbolAddress((void**)&pR,   g_R);
    cudaGetSymbolAddress((void**)&pisc, g_isc);
    cudaGetSymbolAddress((void**)&pselidx, g_selidx);
    cudaGetSymbolAddress((void**)&pselcnt, g_selcnt);
    cudaGetSymbolAddress((void**)&po,   g_o);
    cudaGetSymbolAddress((void**)&poa,  g_oa);
    cudaGetSymbolAddress((void**)&ph,   g_h);
    cudaGetSymbolAddress((void**)&px2,  g_x2);
    cudaGetSymbolAddress((void**)&pgu,  g_gu);
    cudaGetSymbolAddress((void**)&pact, g_act);
    cudaGetSymbolAddress((void**)&pRC,  g_ropeC);
    cudaGetSymbolAddress((void**)&pRS,  g_ropeS);

    cudaFuncSetAttribute(tgemm_kernel<false>,
                         cudaFuncAttributeMaxDynamicSharedMemorySize, SMEM_PIPE_BYTES);
    cudaFuncSetAttribute(tgemm_kernel<true>,
                         cudaFuncAttributeMaxDynamicSharedMemorySize, SMEM_PIPE_BYTES);

    // 0) rope table
    rope_table_kernel<<<(T_ * 32 + 255) / 256, 256>>>(pRC, pRS);

    // 1) x = rms(hidden, ln1)
    rms_kernel<<<T_, 256>>>(hidden, ln1_w, px, DIM_);

    // 2) qr = rms(x @ wq_a, q_norm)
    tgemm_kernel<false><<<ggrid(T_, QL_), 256, SMEM_PIPE_BYTES>>>(T_, QL_, DIM_, px, DIM_, wq_a, QL_, nullptr, pqr, QL_);
    rms_kernel<<<T_, 256>>>(pqr, q_norm_w, pqr, QL_);

    // 3) q / qi projections + rope
    tgemm_kernel<false><<<ggrid(T_, H_*DH_), 256, SMEM_PIPE_BYTES>>>(T_, H_*DH_, QL_, pqr, QL_, wq_b, H_*DH_, nullptr, pq, H_*DH_);
    tgemm_kernel<false><<<ggrid(T_, HI_*DI_), 256, SMEM_PIPE_BYTES>>>(T_, HI_*DI_, QL_, pqr, QL_, idx_wq_b, HI_*DI_, nullptr, pqi, HI_*DI_);
    rope_apply_kernel<<<T_ * H_ / 8,  256>>>(pq,  positions, pRC, pRS, H_,  DH_, NOPE_,  0, T_ * H_);
    rope_apply_kernel<<<T_ * HI_ / 8, 256>>>(pqi, positions, pRC, pRS, HI_, DI_, INOPE_, 0, T_ * HI_);

    // 4) kvc compression + rope
    tgemm_kernel<false><<<ggrid(T_, 2*DH_), 256, SMEM_PIPE_BYTES>>>(T_, 2*DH_, DIM_, px, DIM_, comp_wkv,   2*DH_, nullptr, pkvA, 2*DH_);
    tgemm_kernel<false><<<ggrid(T_, 2*DH_), 256, SMEM_PIPE_BYTES>>>(T_, 2*DH_, DIM_, px, DIM_, comp_wgate, 2*DH_, nullptr, pkvG, 2*DH_);
    kvgate_kernel<<<(T_ * 2 * DH_ + 255) / 256, 256>>>(pkvA, pkvG, comp_ape, pkvF, 2*DH_);
    compress_kernel<<<SC_, DH_>>>(pkvF, comp_norm_w, pkvc, DH_);
    rope_apply_kernel<<<SC_ / 8, 256>>>(pkvc, positions, pRC, pRS, 1, DH_, NOPE_, 1, SC_);

    // 5) ki compression + rope + transpose
    tgemm_kernel<false><<<ggrid(T_, 2*DI_), 256, SMEM_PIPE_BYTES>>>(T_, 2*DI_, DIM_, px, DIM_, icomp_wkv,   2*DI_, nullptr, pikA, 2*DI_);
    tgemm_kernel<false><<<ggrid(T_, 2*DI_), 256, SMEM_PIPE_BYTES>>>(T_, 2*DI_, DIM_, px, DIM_, icomp_wgate, 2*DI_, nullptr, pikG, 2*DI_);
    kvgate_kernel<<<(T_ * 2 * DI_ + 255) / 256, 256>>>(pikA, pikG, icomp_ape, pikF, 2*DI_);
    compress_kernel<<<SC_, DI_>>>(pikF, icomp_norm_w, pki, DI_);
    rope_apply_kernel<<<SC_ / 8, 256>>>(pki, positions, pRC, pRS, 1, DI_, INOPE_, 1, SC_);
    transpose_kernel<<<dim3(DI_/32, SC_/32, 1), dim3(32, 8)>>>(pki, pkiT, SC_, DI_);

    // 6) iw
    tgemm_kernel<false><<<ggrid(T_, HI_), 256, SMEM_PIPE_BYTES>>>(T_, HI_, DIM_, px, DIM_, idx_wproj, HI_, nullptr, piw, HI_);

    // 7) R = qi @ kiT ; iscore reduce
    tgemm_kernel<false><<<ggrid(T_*HI_, SC_), 256, SMEM_PIPE_BYTES>>>(T_*HI_, SC_, DI_, pqi, DI_, pkiT, SC_, nullptr, pR, SC_);
    iscore_reduce_kernel<<<T_, 256>>>(pR, piw, pisc);

    // 8) top-256
    topk_kernel<<<T_, 256>>>(pisc, pselidx, pselcnt);

    // 9) head-shared flash attention
    attn2_kernel<<<T_, 512>>>(pq, pkvc, pselidx, pselcnt, attn_sink, po);

    // 10) output proj: transpose wo_a, then 4 pipelined GEMMs, then wo_b (+residual)
    transpose_kernel<<<dim3(FG_/32, OLORA_/32, G_), dim3(32, 8)>>>(wo_a, pwoaT, OLORA_, FG_);
    for (int g = 0; g < G_; g++) {
        tgemm_kernel<false><<<ggrid(T_, OLORA_), 256, SMEM_PIPE_BYTES>>>(
            T_, OLORA_, FG_,
            po + g * FG_, H_*DH_,
            pwoaT + (size_t)g * FG_ * OLORA_, OLORA_,
            nullptr, poa + g * OLORA_, G_*OLORA_);
    }
    tgemm_kernel<true><<<ggrid(T_, DIM_), 256, SMEM_PIPE_BYTES>>>(T_, DIM_, G_*OLORA_, poa, G_*OLORA_, wo_b, DIM_, hidden, ph, DIM_);

    // 11) MLP
    rms_kernel<<<T_, 256>>>(ph, ln2_w, px2, DIM_);
    tgemm_kernel<false><<<ggrid(T_, 2*II_), 256, SMEM_PIPE_BYTES>>>(T_, 2*II_, DIM_, px2, DIM_, gate_up_w, 2*II_, nullptr, pgu, 2*II_);
    silu_kernel<<<(int)(((size_t)T_ * II_ + 255) / 256), 256>>>(pgu, pact);
    tgemm_kernel<true><<<ggrid(T_, DIM_), 256, SMEM_PIPE_BYTES>>>(T_, DIM_, II_, pact, II_, down_w, DIM_, ph, out, DIM_);
}

// round 5
// speedup vs baseline: 3.9280x; 1.0161x over previous
#include <cuda_runtime.h>
#include <math.h>
#include <stdint.h>

// ---------------- problem constants ----------------
#define T_    2048
#define DIM_  2048
#define QL_   1536
#define H_    16
#define DH_   256
#define NOPE_ 192
#define HI_   32
#define DI_   128
#define INOPE_ 64
#define SC_   512
#define TOPK_ 256
#define II_   8192
#define G_    4
#define OLORA_ 512
#define FG_   1024
#define EPSF  1e-6f
#define NEGF  (-1e30f)
#define SCALE_   0.0625f
#define ISCALE_  0.08838834764831845f
#define LOG_THETA 11.98292909421596506

// ---------------- scratch ----------------
__device__ float g_x   [T_ * DIM_];
__device__ float g_qr  [T_ * QL_];
__device__ float g_q   [T_ * H_ * DH_];
__device__ float g_qi  [T_ * HI_ * DI_];
__device__ float g_kvA [T_ * 2 * DH_];
__device__ float g_kvF [T_ * 2 * DH_];
__device__ float g_kvc [SC_ * DH_];
__device__ float g_ikA [T_ * 2 * DI_];
__device__ float g_ikF [T_ * 2 * DI_];
__device__ float g_ki  [SC_ * DI_];
__device__ float g_kiT [DI_ * SC_];
__device__ float g_woaT[G_ * FG_ * OLORA_];
__device__ float g_iw  [T_ * HI_];
__device__ float g_isc [T_ * SC_];
__device__ int   g_selidx[T_ * TOPK_];
__device__ int   g_selcnt[T_];
__device__ float g_o   [T_ * H_ * DH_];
__device__ float g_oa  [T_ * G_ * OLORA_];
__device__ float g_h   [T_ * DIM_];
__device__ float g_x2  [T_ * DIM_];
__device__ float g_act [(size_t)T_ * II_];
__device__ float g_ropeC[T_ * 32];
__device__ float g_ropeS[T_ * 32];

// ---------------- reductions ----------------
__device__ __forceinline__ float blockReduceSum(float v) {
    __shared__ float sh[32];
    int lane = threadIdx.x & 31, wid = threadIdx.x >> 5;
    #pragma unroll
    for (int o = 16; o > 0; o >>= 1) v += __shfl_xor_sync(0xffffffffu, v, o);
    if (lane == 0) sh[wid] = v;
    __syncthreads();
    int nw = (blockDim.x + 31) >> 5;
    if (wid == 0) {
        float r = (lane < nw) ? sh[lane] : 0.0f;
        #pragma unroll
        for (int o = 16; o > 0; o >>= 1) r += __shfl_xor_sync(0xffffffffu, r, o);
        if (lane == 0) sh[0] = r;
    }
    __syncthreads();
    float res = sh[0];
    __syncthreads();
    return res;
}

// ---------------- tf32 / cp.async helpers ----------------
__device__ __forceinline__ uint32_t f2tf32(float x) {
    uint32_t r;
    asm("cvt.rna.tf32.f32 %0, %1;" : "=r"(r) : "f"(x));
    return r;
}

__device__ __forceinline__ void mma_tf32(float* d, const uint32_t* a, const uint32_t* b) {
    asm volatile(
        "mma.sync.aligned.m16n8k8.row.col.f32.tf32.tf32.f32 "
        "{%0,%1,%2,%3}, {%4,%5,%6,%7}, {%8,%9}, {%0,%1,%2,%3};"
        : "+f"(d[0]), "+f"(d[1]), "+f"(d[2]), "+f"(d[3])
        : "r"(a[0]), "r"(a[1]), "r"(a[2]), "r"(a[3]), "r"(b[0]), "r"(b[1]));
}

__device__ __forceinline__ void cp16(float* smem_dst, const float* gsrc, bool pred) {
    uint32_t s = (uint32_t)__cvta_generic_to_shared(smem_dst);
    int sz = pred ? 16 : 0;
    asm volatile("cp.async.cg.shared.global [%0], [%1], 16, %2;\n"
                 :: "r"(s), "l"(gsrc), "r"(sz));
}
#define CP_COMMIT() asm volatile("cp.async.commit_group;" ::: "memory")
#define CP_WAIT1()  asm volatile("cp.async.wait_group 1;" ::: "memory")
#define CP_WAIT0()  asm volatile("cp.async.wait_group 0;" ::: "memory")

// ---------------- epilogue modes ----------------
#define EP_NONE  0
#define EP_ADD   1   // C = acc + Cadd
#define EP_GATE  2   // C = Cadd * sigmoid(acc) + aux[(r&3)*N + c]
#define EP_SILU  3   // C = silu(Cadd) * acc
#define EP_RFUSE 4   // isc fusion: Cadd=iw, C=isc; nothing else written

// ---------------- tensor-core TF32 GEMM, 128x128x32, 3-stage pipeline ----------------
#define BM 128
#define BN 128
#define BK 32
#define AS_S 36
#define BS_S 136
#define A_TILE (BM * AS_S)
#define B_TILE (BK * BS_S)
#define STAGE_F (A_TILE + B_TILE)
#define SMEM_PIPE_BYTES (STAGE_F * 3 * 4)   // 107520

template<int EP>
__global__ void __launch_bounds__(256, 2) tgemm_kernel(
    int M, int N, int K,
    const float* __restrict__ A, int lda,
    const float* __restrict__ B, int ldb,
    const float* __restrict__ Cadd,
    const float* __restrict__ aux,
    float* __restrict__ C, int ldc)
{
    extern __shared__ float smem[];
    const int bm = blockIdx.y * BM;
    const int bn = blockIdx.x * BN;
    const int tid = threadIdx.x;
    const int lane = tid & 31;
    const int wid = tid >> 5;
    const int wm = wid & 3;
    const int wn = wid >> 2;
    const int gid = lane >> 2;
    const int tig = lane & 3;

    float acc[2][8][4];
    #pragma unroll
    for (int mi = 0; mi < 2; mi++)
        #pragma unroll
        for (int ni = 0; ni < 8; ni++)
            #pragma unroll
            for (int r = 0; r < 4; r++) acc[mi][ni][r] = 0.0f;

    const int nIter = K / BK;

    auto issue = [&](int st, int k0) {
        float* sA = smem + st * STAGE_F;
        float* sB = sA + A_TILE;
        #pragma unroll
        for (int i = 0; i < 4; i++) {
            int f = tid + i * 256;
            int r = f >> 3, q = f & 7;
            int gr = bm + r;
            cp16(&sA[r * AS_S + 4 * q], A + (size_t)gr * lda + k0 + 4 * q, gr < M);
        }
        #pragma unroll
        for (int i = 0; i < 4; i++) {
            int f = tid + i * 256;
            int k = f >> 5, q = f & 31;
            int gc = bn + 4 * q;
            cp16(&sB[k * BS_S + 4 * q], B + (size_t)(k0 + k) * ldb + gc, gc < N);
        }
    };

    auto frag_compute = [&](int st) {
        const float* sA = smem + st * STAGE_F;
        const float* sB = sA + A_TILE;
        #pragma unroll
        for (int kk = 0; kk < 4; kk++) {
            const int kb = kk * 8;
            uint32_t af[2][4];
            uint32_t bf[8][2];
            #pragma unroll
            for (int mi = 0; mi < 2; mi++) {
                int r = wm * 32 + mi * 16 + gid;
                af[mi][0] = f2tf32(sA[r * AS_S + kb + tig]);
                af[mi][1] = f2tf32(sA[(r + 8) * AS_S + kb + tig]);
                af[mi][2] = f2tf32(sA[r * AS_S + kb + tig + 4]);
                af[mi][3] = f2tf32(sA[(r + 8) * AS_S + kb + tig + 4]);
            }
            #pragma unroll
            for (int ni = 0; ni < 8; ni++) {
                int c = wn * 64 + ni * 8 + gid;
                bf[ni][0] = f2tf32(sB[(kb + tig) * BS_S + c]);
                bf[ni][1] = f2tf32(sB[(kb + tig + 4) * BS_S + c]);
            }
            #pragma unroll
            for (int mi = 0; mi < 2; mi++)
                #pragma unroll
                for (int ni = 0; ni < 8; ni++)
                    mma_tf32(acc[mi][ni], af[mi], bf[ni]);
        }
    };

    issue(0, 0);
    CP_COMMIT();
    if (nIter > 1) { issue(1, BK); CP_COMMIT(); }

    int st = 0;
    for (int it = 0; it < nIter; ++it) {
        if (it + 1 < nIter) CP_WAIT1(); else CP_WAIT0();
        __syncthreads();
        if (it + 2 < nIter) {
            int st2 = st + 2; if (st2 >= 3) st2 -= 3;
            issue(st2, (it + 2) * BK);
            CP_COMMIT();
        }
        frag_compute(st);
        if (++st == 3) st = 0;
    }

    // ---------------- epilogues ----------------
    if (EP == EP_RFUSE) {
        // rows of this warp = token t (all 32 heads); reduce over h in-warp.
        int t = bm / HI_ + wm;
        float wA = Cadd[t * HI_ + gid];
        float wB = Cadd[t * HI_ + gid + 8];
        float wC = Cadd[t * HI_ + gid + 16];
        float wD = Cadd[t * HI_ + gid + 24];
        #pragma unroll
        for (int ni = 0; ni < 8; ni++) {
            float p0 = wA * fmaxf(acc[0][ni][0], 0.f) + wB * fmaxf(acc[0][ni][2], 0.f)
                     + wC * fmaxf(acc[1][ni][0], 0.f) + wD * fmaxf(acc[1][ni][2], 0.f);
            float p1 = wA * fmaxf(acc[0][ni][1], 0.f) + wB * fmaxf(acc[0][ni][3], 0.f)
                     + wC * fmaxf(acc[1][ni][1], 0.f) + wD * fmaxf(acc[1][ni][3], 0.f);
            #pragma unroll
            for (int off = 4; off < 32; off <<= 1) {
                p0 += __shfl_xor_sync(0xffffffffu, p0, off);
                p1 += __shfl_xor_sync(0xffffffffu, p1, off);
            }
            if (gid == 0) {
                int c = bn + wn * 64 + ni * 8 + tig * 2;
                C[(size_t)t * ldc + c]     = p0 * ISCALE_;
                C[(size_t)t * ldc + c + 1] = p1 * ISCALE_;
            }
        }
        return;
    }

    #pragma unroll
    for (int mi = 0; mi < 2; mi++) {
        int r0 = bm + wm * 32 + mi * 16 + gid;
        int r1 = r0 + 8;
        #pragma unroll
        for (int ni = 0; ni < 8; ni++) {
            int c = bn + wn * 64 + ni * 8 + tig * 2;
            float* ap = acc[mi][ni];
            if (c < N) {
                #pragma unroll
                for (int half = 0; half < 2; half++) {
                    int r = half ? r1 : r0;
                    if (r >= M) continue;
                    float a0 = ap[half * 2], a1 = ap[half * 2 + 1];
                    float v0, v1;
                    if (EP == EP_NONE) {
                        v0 = a0; v1 = a1;
                    } else if (EP == EP_ADD) {
                        float2 cc = *(const float2*)(Cadd + (size_t)r * ldc + c);
                        v0 = a0 + cc.x; v1 = a1 + cc.y;
                    } else if (EP == EP_GATE) {
                        float2 kv = *(const float2*)(Cadd + (size_t)r * ldc + c);
                        float2 ap2 = *(const float2*)(aux + (size_t)(r & 3) * N + c);
                        v0 = kv.x / (1.0f + expf(-a0)) + ap2.x;
                        v1 = kv.y / (1.0f + expf(-a1)) + ap2.y;
                    } else { // EP_SILU
                        float2 gg = *(const float2*)(Cadd + (size_t)r * ldc + c);
                        v0 = gg.x / (1.0f + expf(-gg.x)) * a0;
                        v1 = gg.y / (1.0f + expf(-gg.y)) * a1;
                    }
                    *(float2*)(C + (size_t)r * ldc + c) = make_float2(v0, v1);
                }
            }
        }
    }
}

// ---------------- tiled transpose ----------------
__global__ void transpose_kernel(const float* __restrict__ in, float* __restrict__ out,
                                 int R, int C)
{
    __shared__ float tile[32][33];
    const float* inz = in + (size_t)blockIdx.z * R * C;
    float* outz = out + (size_t)blockIdx.z * R * C;
    int bx = blockIdx.x * 32, by = blockIdx.y * 32;
    int x = bx + threadIdx.x;
    #pragma unroll
    for (int i = 0; i < 4; i++) {
        int y = by + threadIdx.y + 8 * i;
        if (y < R && x < C) tile[threadIdx.y + 8 * i][threadIdx.x] = inz[(size_t)y * C + x];
    }
    __syncthreads();
    int x2 = by + threadIdx.x;
    #pragma unroll
    for (int i = 0; i < 4; i++) {
        int y2 = bx + threadIdx.y + 8 * i;
        if (y2 < C && x2 < R) outz[(size_t)y2 * R + x2] = tile[threadIdx.x][threadIdx.y + 8 * i];
    }
}

// ---------------- rmsnorm ----------------
__global__ void rms_kernel(const float* __restrict__ in, const float* __restrict__ w,
                           float* __restrict__ out, int D)
{
    int t = blockIdx.x;
    const float* row = in + (size_t)t * D;
    float s = 0.0f;
    for (int d = threadIdx.x; d < D; d += blockDim.x) { float v = row[d]; s += v * v; }
    s = blockReduceSum(s);
    float inv = rsqrtf(s / (float)D + EPSF);
    for (int d = threadIdx.x; d < D; d += blockDim.x)
        out[(size_t)t * D + d] = row[d] * inv * w[d];
}

// ---------------- compress ----------------
__global__ void compress_kernel(const float* __restrict__ kvf, const float* __restrict__ w,
                                float* __restrict__ out, int d)
{
    int b = blockIdx.x;
    int e = threadIdx.x;
    int W = 2 * d;
    float m = 0.0f;
    if (b > 0) {
        #pragma unroll
        for (int r = 0; r < 4; r++) m += kvf[(size_t)((b - 1) * 4 + r) * W + e];
    }
    #pragma unroll
    for (int r = 0; r < 4; r++) m += kvf[(size_t)(b * 4 + r) * W + d + e];
    m *= 0.125f;
    float ssq = blockReduceSum(m * m);
    float inv = rsqrtf(ssq / (float)d + EPSF);
    out[(size_t)b * d + e] = m * inv * w[e];
}

// ---------------- RoPE table ----------------
__global__ void rope_table_kernel(float* __restrict__ tc, float* __restrict__ ts)
{
    int i = blockIdx.x * blockDim.x + threadIdx.x;
    if (i >= T_ * 32) return;
    int pos = i >> 5, f = i & 31;
    double freq = exp(-((double)(2 * f) / 64.0) * LOG_THETA);
    double ang = (double)pos * freq;
    tc[i] = (float)cos(ang);
    ts[i] = (float)sin(ang);
}

// ---------------- RoPE apply ----------------
__global__ void rope_apply_kernel(float* __restrict__ x, const int* __restrict__ positions,
                                  const float* __restrict__ tc, const float* __restrict__ ts,
                                  int Hh, int Dd, int ropeOff, int compPos, int nRows)
{
    int row = blockIdx.x * 8 + (threadIdx.x >> 5);
    if (row >= nRows) return;
    int lane = threadIdx.x & 31;
    int t = row / Hh;
    int pos = compPos ? (4 * (t + 1) - 1) : positions[t];
    float c = tc[pos * 32 + lane], s = ts[pos * 32 + lane];
    float* p = x + (size_t)row * Dd + ropeOff;
    float x0 = p[2 * lane], x1 = p[2 * lane + 1];
    p[2 * lane]     = x0 * c - x1 * s;
    p[2 * lane + 1] = x0 * s + x1 * c;
}

// ---------------- exact top-256 ----------------
__global__ void topk_kernel(const float* __restrict__ isc, int* __restrict__ selidx,
                            int* __restrict__ selcnt)
{
    int t = blockIdx.x;
    __shared__ float sv[SC_];
    __shared__ int   si[SC_];
    int tid = threadIdx.x;
    int visCount = (t >= 3) ? ((t - 3) / 4 + 1) : 0;
    for (int i = tid; i < SC_; i += 256) {
        sv[i] = (i < visCount) ? isc[t * SC_ + i] : NEGF;
        si[i] = i;
    }
    __syncthreads();
    for (int k = 2; k <= SC_; k <<= 1) {
        for (int j = k >> 1; j > 0; j >>= 1) {
            for (int base = tid; base < SC_; base += 256) {
                int partner = base ^ j;
                if (partner > base) {
                    bool up = ((base & k) == 0);
                    float va = sv[base], vb = sv[partner];
                    int ia = si[base], ib = si[partner];
                    bool aFirst = (va > vb) || (va == vb && ia < ib);
                    if (up ? !aFirst : aFirst) {
                        sv[base] = vb; sv[partner] = va;
                        si[base] = ib; si[partner] = ia;
                    }
                }
            }
            __syncthreads();
        }
    }
    int cnt = min(visCount, TOPK_);
    if (tid == 0) selcnt[t] = cnt;
    for (int r = tid; r < cnt; r += 256) selidx[t * TOPK_ + r] = si[r];
}

// ---------------- head-shared flash attention ----------------
__global__ void __launch_bounds__(512) attn2_kernel(
    const float* __restrict__ q, const float* __restrict__ kvc,
    const int* __restrict__ selidx, const int* __restrict__ selcnt,
    const float* __restrict__ sink, float* __restrict__ o)
{
    __shared__ float kt[32][DH_];
    __shared__ int   ss[TOPK_];
    int t = blockIdx.x;
    int tid = threadIdx.x, lane = tid & 31, w = tid >> 5;
    int cnt = selcnt[t];
    for (int i = tid; i < cnt; i += 512) ss[i] = selidx[t * TOPK_ + i];
    __syncthreads();

    float q8[8];
    const float* qp = q + ((size_t)t * H_ + w) * DH_;
    #pragma unroll
    for (int i = 0; i < 8; i++) q8[i] = qp[lane + 32 * i];

    float m = NEGF, se = 0.0f;
    float acc[8] = {};

    for (int j0 = 0; j0 < cnt; j0 += 32) {
        int rem = min(32, cnt - j0);
        __syncthreads();
        for (int f = tid; f < 32 * 64; f += 512) {
            int r = f >> 6, c4 = f & 63;
            float4 v = make_float4(0.f, 0.f, 0.f, 0.f);
            if (r < rem) v = *(const float4*)(kvc + (size_t)ss[j0 + r] * DH_ + 4 * c4);
            *(float4*)&kt[r][4 * c4] = v;
        }
        __syncthreads();
        for (int j = 0; j < rem; j++) {
            float dot = 0.0f;
            #pragma unroll
            for (int i = 0; i < 8; i++) dot += q8[i] * kt[j][lane + 32 * i];
            #pragma unroll
            for (int off = 16; off > 0; off >>= 1)
                dot += __shfl_xor_sync(0xffffffffu, dot, off);
            float lg = dot * SCALE_;
            float mn = fmaxf(m, lg);
            float sc = expf(m - mn);
            float p  = expf(lg - mn);
            se = se * sc + p;
            #pragma unroll
            for (int i = 0; i < 8; i++)
                acc[i] = acc[i] * sc + p * kt[j][lane + 32 * i];
            m = mn;
        }
    }

    float snk = sink[w];
    float mn = fmaxf(m, snk);
    float sc = expf(m - mn);
    se = se * sc + expf(snk - mn);
    float inv = 1.0f / se;
    float* op = o + ((size_t)t * H_ + w) * DH_;
    #pragma unroll
    for (int i = 0; i < 8; i++) op[lane + 32 * i] = acc[i] * sc * inv;
}

// ---------------- host ----------------
static inline dim3 ggrid(int M, int N) { return dim3((N + BN - 1) / BN, (M + BM - 1) / BM); }

extern "C" void kernel_launch(void* const* d_in, const int* in_sizes, int n_in,
                              void* d_out, int out_size)
{
    const float* hidden      = (const float*)d_in[0];
    const int*   positions   = (const int*)  d_in[1];
    const float* ln1_w       = (const float*)d_in[2];
    const float* ln2_w       = (const float*)d_in[3];
    const float* wq_a        = (const float*)d_in[4];
    const float* q_norm_w    = (const float*)d_in[5];
    const float* wq_b        = (const float*)d_in[6];
    const float* comp_wkv    = (const float*)d_in[7];
    const float* comp_wgate  = (const float*)d_in[8];
    const float* comp_ape    = (const float*)d_in[9];
    const float* comp_norm_w = (const float*)d_in[10];
    const float* idx_wq_b    = (const float*)d_in[11];
    const float* idx_wproj   = (const float*)d_in[12];
    const float* icomp_wkv   = (const float*)d_in[13];
    const float* icomp_wgate = (const float*)d_in[14];
    const float* icomp_ape   = (const float*)d_in[15];
    const float* icomp_norm_w= (const float*)d_in[16];
    const float* attn_sink   = (const float*)d_in[17];
    const float* wo_a        = (const float*)d_in[18];
    const float* wo_b        = (const float*)d_in[19];
    const float* gate_up_w   = (const float*)d_in[20];
    const float* down_w      = (const float*)d_in[21];
    float* out = (float*)d_out;

    float *px, *pqr, *pq, *pqi, *pkvA, *pkvF, *pkvc;
    float *pikA, *pikF, *pki, *pkiT, *pwoaT, *piw, *pisc, *po, *poa, *ph, *px2, *pact;
    float *pRC, *pRS;
    int *pselidx, *pselcnt;
    cudaGetSymbolAddress((void**)&px,   g_x);
    cudaGetSymbolAddress((void**)&pqr,  g_qr);
    cudaGetSymbolAddress((void**)&pq,   g_q);
    cudaGetSymbolAddress((void**)&pqi,  g_qi);
    cudaGetSymbolAddress((void**)&pkvA, g_kvA);
    cudaGetSymbolAddress((void**)&pkvF, g_kvF);
    cudaGetSymbolAddress((void**)&pkvc, g_kvc);
    cudaGetSymbolAddress((void**)&pikA, g_ikA);
    cudaGetSymbolAddress((void**)&pikF, g_ikF);
    cudaGetSymbolAddress((void**)&pki,  g_ki);
    cudaGetSymbolAddress((void**)&pkiT, g_kiT);
    cudaGetSymbolAddress((void**)&pwoaT,g_woaT);
    cudaGetSymbolAddress((void**)&piw,  g_iw);
    cudaGetSymbolAddress((void**)&pisc, g_isc);
    cudaGetSymbolAddress((void**)&pselidx, g_selidx);
    cudaGetSymbolAddress((void**)&pselcnt, g_selcnt);
    cudaGetSymbolAddress((void**)&po,   g_o);
    cudaGetSymbolAddress((void**)&poa,  g_oa);
    cudaGetSymbolAddress((void**)&ph,   g_h);
    cudaGetSymbolAddress((void**)&px2,  g_x2);
    cudaGetSymbolAddress((void**)&pact, g_act);
    cudaGetSymbolAddress((void**)&pRC,  g_ropeC);
    cudaGetSymbolAddress((void**)&pRS,  g_ropeS);

    cudaFuncSetAttribute(tgemm_kernel<EP_NONE>,  cudaFuncAttributeMaxDynamicSharedMemorySize, SMEM_PIPE_BYTES);
    cudaFuncSetAttribute(tgemm_kernel<EP_ADD>,   cudaFuncAttributeMaxDynamicSharedMemorySize, SMEM_PIPE_BYTES);
    cudaFuncSetAttribute(tgemm_kernel<EP_GATE>,  cudaFuncAttributeMaxDynamicSharedMemorySize, SMEM_PIPE_BYTES);
    cudaFuncSetAttribute(tgemm_kernel<EP_SILU>,  cudaFuncAttributeMaxDynamicSharedMemorySize, SMEM_PIPE_BYTES);
    cudaFuncSetAttribute(tgemm_kernel<EP_RFUSE>, cudaFuncAttributeMaxDynamicSharedMemorySize, SMEM_PIPE_BYTES);

    // 0) rope table
    rope_table_kernel<<<(T_ * 32 + 255) / 256, 256>>>(pRC, pRS);

    // 1) x = rms(hidden, ln1)
    rms_kernel<<<T_, 256>>>(hidden, ln1_w, px, DIM_);

    // 2) qr = rms(x @ wq_a, q_norm)
    tgemm_kernel<EP_NONE><<<ggrid(T_, QL_), 256, SMEM_PIPE_BYTES>>>(T_, QL_, DIM_, px, DIM_, wq_a, QL_, nullptr, nullptr, pqr, QL_);
    rms_kernel<<<T_, 256>>>(pqr, q_norm_w, pqr, QL_);

    // 3) q / qi projections + rope
    tgemm_kernel<EP_NONE><<<ggrid(T_, H_*DH_), 256, SMEM_PIPE_BYTES>>>(T_, H_*DH_, QL_, pqr, QL_, wq_b, H_*DH_, nullptr, nullptr, pq, H_*DH_);
    tgemm_kernel<EP_NONE><<<ggrid(T_, HI_*DI_), 256, SMEM_PIPE_BYTES>>>(T_, HI_*DI_, QL_, pqr, QL_, idx_wq_b, HI_*DI_, nullptr, nullptr, pqi, HI_*DI_);
    rope_apply_kernel<<<T_ * H_ / 8,  256>>>(pq,  positions, pRC, pRS, H_,  DH_, NOPE_,  0, T_ * H_);
    rope_apply_kernel<<<T_ * HI_ / 8, 256>>>(pqi, positions, pRC, pRS, HI_, DI_, INOPE_, 0, T_ * HI_);

    // 4) kvc: wkv GEMM, then wgate GEMM with fused sigmoid-gate + ape
    tgemm_kernel<EP_NONE><<<ggrid(T_, 2*DH_), 256, SMEM_PIPE_BYTES>>>(T_, 2*DH_, DIM_, px, DIM_, comp_wkv, 2*DH_, nullptr, nullptr, pkvA, 2*DH_);
    tgemm_kernel<EP_GATE><<<ggrid(T_, 2*DH_), 256, SMEM_PIPE_BYTES>>>(T_, 2*DH_, DIM_, px, DIM_, comp_wgate, 2*DH_, pkvA, comp_ape, pkvF, 2*DH_);
    compress_kernel<<<SC_, DH_>>>(pkvF, comp_norm_w, pkvc, DH_);
    rope_apply_kernel<<<SC_ / 8, 256>>>(pkvc, positions, pRC, pRS, 1, DH_, NOPE_, 1, SC_);

    // 5) ki: same fused pattern + rope + transpose
    tgemm_kernel<EP_NONE><<<ggrid(T_, 2*DI_), 256, SMEM_PIPE_BYTES>>>(T_, 2*DI_, DIM_, px, DIM_, icomp_wkv, 2*DI_, nullptr, nullptr, pikA, 2*DI_);
    tgemm_kernel<EP_GATE><<<ggrid(T_, 2*DI_), 256, SMEM_PIPE_BYTES>>>(T_, 2*DI_, DIM_, px, DIM_, icomp_wgate, 2*DI_, pikA, icomp_ape, pikF, 2*DI_);
    compress_kernel<<<SC_, DI_>>>(pikF, icomp_norm_w, pki, DI_);
    rope_apply_kernel<<<SC_ / 8, 256>>>(pki, positions, pRC, pRS, 1, DI_, INOPE_, 1, SC_);
    transpose_kernel<<<dim3(DI_/32, SC_/32, 1), dim3(32, 8)>>>(pki, pkiT, SC_, DI_);

    // 6) iw
    tgemm_kernel<EP_NONE><<<ggrid(T_, HI_), 256, SMEM_PIPE_BYTES>>>(T_, HI_, DIM_, px, DIM_, idx_wproj, HI_, nullptr, nullptr, piw, HI_);

    // 7) R GEMM with fused weighted-relu head reduction -> isc directly (R never materialized)
    tgemm_kernel<EP_RFUSE><<<ggrid(T_*HI_, SC_), 256, SMEM_PIPE_BYTES>>>(T_*HI_, SC_, DI_, pqi, DI_, pkiT, SC_, piw, nullptr, pisc, SC_);

    // 8) top-256
    topk_kernel<<<T_, 256>>>(pisc, pselidx, pselcnt);

    // 9) head-shared flash attention
    attn2_kernel<<<T_, 512>>>(pq, pkvc, pselidx, pselcnt, attn_sink, po);

    // 10) output proj
    transpose_kernel<<<dim3(FG_/32, OLORA_/32, G_), dim3(32, 8)>>>(wo_a, pwoaT, OLORA_, FG_);
    for (int g = 0; g < G_; g++) {
        tgemm_kernel<EP_NONE><<<ggrid(T_, OLORA_), 256, SMEM_PIPE_BYTES>>>(
            T_, OLORA_, FG_,
            po + g * FG_, H_*DH_,
            pwoaT + (size_t)g * FG_ * OLORA_, OLORA_,
            nullptr, nullptr, poa + g * OLORA_, G_*OLORA_);
    }
    tgemm_kernel<EP_ADD><<<ggrid(T_, DIM_), 256, SMEM_PIPE_BYTES>>>(T_, DIM_, G_*OLORA_, poa, G_*OLORA_, wo_b, DIM_, hidden, nullptr, ph, DIM_);

    // 11) MLP: gate GEMM -> act; up GEMM fused silu-mul (in place); down GEMM + residual
    rms_kernel<<<T_, 256>>>(ph, ln2_w, px2, DIM_);
    tgemm_kernel<EP_NONE><<<ggrid(T_, II_), 256, SMEM_PIPE_BYTES>>>(T_, II_, DIM_, px2, DIM_, gate_up_w, 2*II_, nullptr, nullptr, pact, II_);
    tgemm_kernel<EP_SILU><<<ggrid(T_, II_), 256, SMEM_PIPE_BYTES>>>(T_, II_, DIM_, px2, DIM_, gate_up_w + II_, 2*II_, pact, nullptr, pact, II_);
    tgemm_kernel<EP_ADD><<<ggrid(T_, DIM_), 256, SMEM_PIPE_BYTES>>>(T_, DIM_, II_, pact, II_, down_w, DIM_, ph, nullptr, out, DIM_);
}

// round 6
// speedup vs baseline: 3.9311x; 1.0008x over previous
#include <cuda_runtime.h>
#include <math.h>
#include <stdint.h>

// ---------------- problem constants ----------------
#define T_    2048
#define DIM_  2048
#define QL_   1536
#define H_    16
#define DH_   256
#define NOPE_ 192
#define HI_   32
#define DI_   128
#define INOPE_ 64
#define SC_   512
#define TOPK_ 256
#define II_   8192
#define G_    4
#define OLORA_ 512
#define FG_   1024
#define EPSF  1e-6f
#define NEGF  (-1e30f)
#define SCALE_   0.0625f
#define ISCALE_  0.08838834764831845f
#define LOG_THETA 11.98292909421596506

// ---------------- scratch ----------------
__device__ float g_x   [T_ * DIM_];
__device__ float g_qr  [T_ * QL_];
__device__ float g_q   [T_ * H_ * DH_];
__device__ float g_qi  [T_ * HI_ * DI_];
__device__ float g_kvA [T_ * 2 * DH_];
__device__ float g_kvF [T_ * 2 * DH_];
__device__ float g_kvc [SC_ * DH_];
__device__ float g_ikA [T_ * 2 * DI_];
__device__ float g_ikF [T_ * 2 * DI_];
__device__ float g_ki  [SC_ * DI_];
__device__ float g_kiT [DI_ * SC_];
__device__ float g_woaT[G_ * FG_ * OLORA_];
__device__ float g_iw  [T_ * HI_];
__device__ float g_isc [T_ * SC_];
__device__ int   g_selidx[T_ * TOPK_];
__device__ int   g_selcnt[T_];
__device__ float g_o   [T_ * H_ * DH_];
__device__ float g_oa  [T_ * G_ * OLORA_];
__device__ float g_h   [T_ * DIM_];
__device__ float g_x2  [T_ * DIM_];
__device__ float g_act [(size_t)T_ * II_];
__device__ float g_ropeC[T_ * 32];
__device__ float g_ropeS[T_ * 32];

// ---------------- reductions ----------------
__device__ __forceinline__ float blockReduceSum(float v) {
    __shared__ float sh[32];
    int lane = threadIdx.x & 31, wid = threadIdx.x >> 5;
    #pragma unroll
    for (int o = 16; o > 0; o >>= 1) v += __shfl_xor_sync(0xffffffffu, v, o);
    if (lane == 0) sh[wid] = v;
    __syncthreads();
    int nw = (blockDim.x + 31) >> 5;
    if (wid == 0) {
        float r = (lane < nw) ? sh[lane] : 0.0f;
        #pragma unroll
        for (int o = 16; o > 0; o >>= 1) r += __shfl_xor_sync(0xffffffffu, r, o);
        if (lane == 0) sh[0] = r;
    }
    __syncthreads();
    float res = sh[0];
    __syncthreads();
    return res;
}

// ---------------- tf32 / cp.async helpers ----------------
__device__ __forceinline__ uint32_t f2tf32(float x) {
    uint32_t r;
    asm("cvt.rna.tf32.f32 %0, %1;" : "=r"(r) : "f"(x));
    return r;
}

__device__ __forceinline__ void mma_tf32(float* d, const uint32_t* a, const uint32_t* b) {
    asm volatile(
        "mma.sync.aligned.m16n8k8.row.col.f32.tf32.tf32.f32 "
        "{%0,%1,%2,%3}, {%4,%5,%6,%7}, {%8,%9}, {%0,%1,%2,%3};"
        : "+f"(d[0]), "+f"(d[1]), "+f"(d[2]), "+f"(d[3])
        : "r"(a[0]), "r"(a[1]), "r"(a[2]), "r"(a[3]), "r"(b[0]), "r"(b[1]));
}

__device__ __forceinline__ void cp16(float* smem_dst, const float* gsrc, bool pred) {
    uint32_t s = (uint32_t)__cvta_generic_to_shared(smem_dst);
    int sz = pred ? 16 : 0;
    asm volatile("cp.async.cg.shared.global [%0], [%1], 16, %2;\n"
                 :: "r"(s), "l"(gsrc), "r"(sz));
}
#define CP_COMMIT() asm volatile("cp.async.commit_group;" ::: "memory")
#define CP_WAIT1()  asm volatile("cp.async.wait_group 1;" ::: "memory")
#define CP_WAIT0()  asm volatile("cp.async.wait_group 0;" ::: "memory")

// ---------------- epilogue modes ----------------
#define EP_NONE  0
#define EP_ADD   1   // C = acc + Cadd
#define EP_GATE  2   // C = Cadd * sigmoid(acc) + aux[(r&3)*N + c]
#define EP_SILU  3   // C = silu(Cadd) * acc
#define EP_RFUSE 4   // isc fusion: Cadd=iw, C=isc; nothing else written

// ---------------- tensor-core TF32 GEMM, 128x128x32, 3-stage pipeline ----------------
#define BM 128
#define BN 128
#define BK 32
#define AS_S 36
#define BS_S 136
#define A_TILE (BM * AS_S)
#define B_TILE (BK * BS_S)
#define STAGE_F (A_TILE + B_TILE)
#define SMEM_PIPE_BYTES (STAGE_F * 3 * 4)   // 107520

template<int EP>
__global__ void __launch_bounds__(256, 2) tgemm_kernel(
    int M, int N, int K,
    const float* __restrict__ A, int lda,
    const float* __restrict__ B, int ldb,
    const float* __restrict__ Cadd,
    const float* __restrict__ aux,
    float* __restrict__ C, int ldc)
{
    extern __shared__ float smem[];
    const int bm = blockIdx.y * BM;
    const int bn = blockIdx.x * BN;
    const int tid = threadIdx.x;
    const int lane = tid & 31;
    const int wid = tid >> 5;
    const int wm = wid & 3;
    const int wn = wid >> 2;
    const int gid = lane >> 2;
    const int tig = lane & 3;

    float acc[2][8][4];
    #pragma unroll
    for (int mi = 0; mi < 2; mi++)
        #pragma unroll
        for (int ni = 0; ni < 8; ni++)
            #pragma unroll
            for (int r = 0; r < 4; r++) acc[mi][ni][r] = 0.0f;

    const int nIter = K / BK;

    auto issue = [&](int st, int k0) {
        float* sA = smem + st * STAGE_F;
        float* sB = sA + A_TILE;
        #pragma unroll
        for (int i = 0; i < 4; i++) {
            int f = tid + i * 256;
            int r = f >> 3, q = f & 7;
            int gr = bm + r;
            cp16(&sA[r * AS_S + 4 * q], A + (size_t)gr * lda + k0 + 4 * q, gr < M);
        }
        #pragma unroll
        for (int i = 0; i < 4; i++) {
            int f = tid + i * 256;
            int k = f >> 5, q = f & 31;
            int gc = bn + 4 * q;
            cp16(&sB[k * BS_S + 4 * q], B + (size_t)(k0 + k) * ldb + gc, gc < N);
        }
    };

    auto frag_compute = [&](int st) {
        const float* sA = smem + st * STAGE_F;
        const float* sB = sA + A_TILE;
        #pragma unroll
        for (int kk = 0; kk < 4; kk++) {
            const int kb = kk * 8;
            uint32_t af[2][4];
            uint32_t bf[8][2];
            #pragma unroll
            for (int mi = 0; mi < 2; mi++) {
                int r = wm * 32 + mi * 16 + gid;
                af[mi][0] = f2tf32(sA[r * AS_S + kb + tig]);
                af[mi][1] = f2tf32(sA[(r + 8) * AS_S + kb + tig]);
                af[mi][2] = f2tf32(sA[r * AS_S + kb + tig + 4]);
                af[mi][3] = f2tf32(sA[(r + 8) * AS_S + kb + tig + 4]);
            }
            #pragma unroll
            for (int ni = 0; ni < 8; ni++) {
                int c = wn * 64 + ni * 8 + gid;
                bf[ni][0] = f2tf32(sB[(kb + tig) * BS_S + c]);
                bf[ni][1] = f2tf32(sB[(kb + tig + 4) * BS_S + c]);
            }
            #pragma unroll
            for (int mi = 0; mi < 2; mi++)
                #pragma unroll
                for (int ni = 0; ni < 8; ni++)
                    mma_tf32(acc[mi][ni], af[mi], bf[ni]);
        }
    };

    issue(0, 0);
    CP_COMMIT();
    if (nIter > 1) { issue(1, BK); CP_COMMIT(); }

    int st = 0;
    for (int it = 0; it < nIter; ++it) {
        if (it + 1 < nIter) CP_WAIT1(); else CP_WAIT0();
        __syncthreads();
        if (it + 2 < nIter) {
            int st2 = st + 2; if (st2 >= 3) st2 -= 3;
            issue(st2, (it + 2) * BK);
            CP_COMMIT();
        }
        frag_compute(st);
        if (++st == 3) st = 0;
    }

    // ---------------- epilogues ----------------
    if (EP == EP_RFUSE) {
        // rows of this warp = token t (all 32 heads); reduce over h in-warp.
        int t = bm / HI_ + wm;
        float wA = Cadd[t * HI_ + gid];
        float wB = Cadd[t * HI_ + gid + 8];
        float wC = Cadd[t * HI_ + gid + 16];
        float wD = Cadd[t * HI_ + gid + 24];
        #pragma unroll
        for (int ni = 0; ni < 8; ni++) {
            float p0 = wA * fmaxf(acc[0][ni][0], 0.f) + wB * fmaxf(acc[0][ni][2], 0.f)
                     + wC * fmaxf(acc[1][ni][0], 0.f) + wD * fmaxf(acc[1][ni][2], 0.f);
            float p1 = wA * fmaxf(acc[0][ni][1], 0.f) + wB * fmaxf(acc[0][ni][3], 0.f)
                     + wC * fmaxf(acc[1][ni][1], 0.f) + wD * fmaxf(acc[1][ni][3], 0.f);
            #pragma unroll
            for (int off = 4; off < 32; off <<= 1) {
                p0 += __shfl_xor_sync(0xffffffffu, p0, off);
                p1 += __shfl_xor_sync(0xffffffffu, p1, off);
            }
            if (gid == 0) {
                int c = bn + wn * 64 + ni * 8 + tig * 2;
                C[(size_t)t * ldc + c]     = p0 * ISCALE_;
                C[(size_t)t * ldc + c + 1] = p1 * ISCALE_;
            }
        }
        return;
    }

    #pragma unroll
    for (int mi = 0; mi < 2; mi++) {
        int r0 = bm + wm * 32 + mi * 16 + gid;
        int r1 = r0 + 8;
        #pragma unroll
        for (int ni = 0; ni < 8; ni++) {
            int c = bn + wn * 64 + ni * 8 + tig * 2;
            float* ap = acc[mi][ni];
            if (c < N) {
                #pragma unroll
                for (int half = 0; half < 2; half++) {
                    int r = half ? r1 : r0;
                    if (r >= M) continue;
                    float a0 = ap[half * 2], a1 = ap[half * 2 + 1];
                    float v0, v1;
                    if (EP == EP_NONE) {
                        v0 = a0; v1 = a1;
                    } else if (EP == EP_ADD) {
                        float2 cc = *(const float2*)(Cadd + (size_t)r * ldc + c);
                        v0 = a0 + cc.x; v1 = a1 + cc.y;
                    } else if (EP == EP_GATE) {
                        float2 kv = *(const float2*)(Cadd + (size_t)r * ldc + c);
                        float2 ap2 = *(const float2*)(aux + (size_t)(r & 3) * N + c);
                        v0 = kv.x / (1.0f + expf(-a0)) + ap2.x;
                        v1 = kv.y / (1.0f + expf(-a1)) + ap2.y;
                    } else { // EP_SILU
                        float2 gg = *(const float2*)(Cadd + (size_t)r * ldc + c);
                        v0 = gg.x / (1.0f + expf(-gg.x)) * a0;
                        v1 = gg.y / (1.0f + expf(-gg.y)) * a1;
                    }
                    *(float2*)(C + (size_t)r * ldc + c) = make_float2(v0, v1);
                }
            }
        }
    }
}

// ---------------- tiled transpose ----------------
__global__ void transpose_kernel(const float* __restrict__ in, float* __restrict__ out,
                                 int R, int C)
{
    __shared__ float tile[32][33];
    const float* inz = in + (size_t)blockIdx.z * R * C;
    float* outz = out + (size_t)blockIdx.z * R * C;
    int bx = blockIdx.x * 32, by = blockIdx.y * 32;
    int x = bx + threadIdx.x;
    #pragma unroll
    for (int i = 0; i < 4; i++) {
        int y = by + threadIdx.y + 8 * i;
        if (y < R && x < C) tile[threadIdx.y + 8 * i][threadIdx.x] = inz[(size_t)y * C + x];
    }
    __syncthreads();
    int x2 = by + threadIdx.x;
    #pragma unroll
    for (int i = 0; i < 4; i++) {
        int y2 = bx + threadIdx.y + 8 * i;
        if (y2 < C && x2 < R) outz[(size_t)y2 * R + x2] = tile[threadIdx.x][threadIdx.y + 8 * i];
    }
}

// ---------------- rmsnorm ----------------
__global__ void rms_kernel(const float* __restrict__ in, const float* __restrict__ w,
                           float* __restrict__ out, int D)
{
    int t = blockIdx.x;
    const float* row = in + (size_t)t * D;
    float s = 0.0f;
    for (int d = threadIdx.x; d < D; d += blockDim.x) { float v = row[d]; s += v * v; }
    s = blockReduceSum(s);
    float inv = rsqrtf(s / (float)D + EPSF);
    for (int d = threadIdx.x; d < D; d += blockDim.x)
        out[(size_t)t * D + d] = row[d] * inv * w[d];
}

// ---------------- compress ----------------
__global__ void compress_kernel(const float* __restrict__ kvf, const float* __restrict__ w,
                                float* __restrict__ out, int d)
{
    int b = blockIdx.x;
    int e = threadIdx.x;
    int W = 2 * d;
    float m = 0.0f;
    if (b > 0) {
        #pragma unroll
        for (int r = 0; r < 4; r++) m += kvf[(size_t)((b - 1) * 4 + r) * W + e];
    }
    #pragma unroll
    for (int r = 0; r < 4; r++) m += kvf[(size_t)(b * 4 + r) * W + d + e];
    m *= 0.125f;
    float ssq = blockReduceSum(m * m);
    float inv = rsqrtf(ssq / (float)d + EPSF);
    out[(size_t)b * d + e] = m * inv * w[e];
}

// ---------------- RoPE table ----------------
__global__ void rope_table_kernel(float* __restrict__ tc, float* __restrict__ ts)
{
    int i = blockIdx.x * blockDim.x + threadIdx.x;
    if (i >= T_ * 32) return;
    int pos = i >> 5, f = i & 31;
    double freq = exp(-((double)(2 * f) / 64.0) * LOG_THETA);
    double ang = (double)pos * freq;
    tc[i] = (float)cos(ang);
    ts[i] = (float)sin(ang);
}

// ---------------- RoPE apply ----------------
__global__ void rope_apply_kernel(float* __restrict__ x, const int* __restrict__ positions,
                                  const float* __restrict__ tc, const float* __restrict__ ts,
                                  int Hh, int Dd, int ropeOff, int compPos, int nRows)
{
    int row = blockIdx.x * 8 + (threadIdx.x >> 5);
    if (row >= nRows) return;
    int lane = threadIdx.x & 31;
    int t = row / Hh;
    int pos = compPos ? (4 * (t + 1) - 1) : positions[t];
    float c = tc[pos * 32 + lane], s = ts[pos * 32 + lane];
    float* p = x + (size_t)row * Dd + ropeOff;
    float x0 = p[2 * lane], x1 = p[2 * lane + 1];
    p[2 * lane]     = x0 * c - x1 * s;
    p[2 * lane + 1] = x0 * s + x1 * c;
}

// ---------------- exact top-256 ----------------
__global__ void topk_kernel(const float* __restrict__ isc, int* __restrict__ selidx,
                            int* __restrict__ selcnt)
{
    int t = blockIdx.x;
    __shared__ float sv[SC_];
    __shared__ int   si[SC_];
    int tid = threadIdx.x;
    int visCount = (t >= 3) ? ((t - 3) / 4 + 1) : 0;
    for (int i = tid; i < SC_; i += 256) {
        sv[i] = (i < visCount) ? isc[t * SC_ + i] : NEGF;
        si[i] = i;
    }
    __syncthreads();
    for (int k = 2; k <= SC_; k <<= 1) {
        for (int j = k >> 1; j > 0; j >>= 1) {
            for (int base = tid; base < SC_; base += 256) {
                int partner = base ^ j;
                if (partner > base) {
                    bool up = ((base & k) == 0);
                    float va = sv[base], vb = sv[partner];
                    int ia = si[base], ib = si[partner];
                    bool aFirst = (va > vb) || (va == vb && ia < ib);
                    if (up ? !aFirst : aFirst) {
                        sv[base] = vb; sv[partner] = va;
                        si[base] = ib; si[partner] = ia;
                    }
                }
            }
            __syncthreads();
        }
    }
    int cnt = min(visCount, TOPK_);
    if (tid == 0) selcnt[t] = cnt;
    for (int r = tid; r < cnt; r += 256) selidx[t * TOPK_ + r] = si[r];
}

// ---------------- head-shared flash attention ----------------
__global__ void __launch_bounds__(512) attn2_kernel(
    const float* __restrict__ q, const float* __restrict__ kvc,
    const int* __restrict__ selidx, const int* __restrict__ selcnt,
    const float* __restrict__ sink, float* __restrict__ o)
{
    __shared__ float kt[32][DH_];
    __shared__ int   ss[TOPK_];
    int t = blockIdx.x;
    int tid = threadIdx.x, lane = tid & 31, w = tid >> 5;
    int cnt = selcnt[t];
    for (int i = tid; i < cnt; i += 512) ss[i] = selidx[t * TOPK_ + i];
    __syncthreads();

    float q8[8];
    const float* qp = q + ((size_t)t * H_ + w) * DH_;
    #pragma unroll
    for (int i = 0; i < 8; i++) q8[i] = qp[lane + 32 * i];

    float m = NEGF, se = 0.0f;
    float acc[8] = {};

    for (int j0 = 0; j0 < cnt; j0 += 32) {
        int rem = min(32, cnt - j0);
        __syncthreads();
        for (int f = tid; f < 32 * 64; f += 512) {
            int r = f >> 6, c4 = f & 63;
            float4 v = make_float4(0.f, 0.f, 0.f, 0.f);
            if (r < rem) v = *(const float4*)(kvc + (size_t)ss[j0 + r] * DH_ + 4 * c4);
            *(float4*)&kt[r][4 * c4] = v;
        }
        __syncthreads();
        for (int j = 0; j < rem; j++) {
            float dot = 0.0f;
            #pragma unroll
            for (int i = 0; i < 8; i++) dot += q8[i] * kt[j][lane + 32 * i];
            #pragma unroll
            for (int off = 16; off > 0; off >>= 1)
                dot += __shfl_xor_sync(0xffffffffu, dot, off);
            float lg = dot * SCALE_;
            float mn = fmaxf(m, lg);
            float sc = expf(m - mn);
            float p  = expf(lg - mn);
            se = se * sc + p;
            #pragma unroll
            for (int i = 0; i < 8; i++)
                acc[i] = acc[i] * sc + p * kt[j][lane + 32 * i];
            m = mn;
        }
    }

    float snk = sink[w];
    float mn = fmaxf(m, snk);
    float sc = expf(m - mn);
    se = se * sc + expf(snk - mn);
    float inv = 1.0f / se;
    float* op = o + ((size_t)t * H_ + w) * DH_;
    #pragma unroll
    for (int i = 0; i < 8; i++) op[lane + 32 * i] = acc[i] * sc * inv;
}

// ---------------- host ----------------
static inline dim3 ggrid(int M, int N) { return dim3((N + BN - 1) / BN, (M + BM - 1) / BM); }

extern "C" void kernel_launch(void* const* d_in, const int* in_sizes, int n_in,
                              void* d_out, int out_size)
{
    const float* hidden      = (const float*)d_in[0];
    const int*   positions   = (const int*)  d_in[1];
    const float* ln1_w       = (const float*)d_in[2];
    const float* ln2_w       = (const float*)d_in[3];
    const float* wq_a        = (const float*)d_in[4];
    const float* q_norm_w    = (const float*)d_in[5];
    const float* wq_b        = (const float*)d_in[6];
    const float* comp_wkv    = (const float*)d_in[7];
    const float* comp_wgate  = (const float*)d_in[8];
    const float* comp_ape    = (const float*)d_in[9];
    const float* comp_norm_w = (const float*)d_in[10];
    const float* idx_wq_b    = (const float*)d_in[11];
    const float* idx_wproj   = (const float*)d_in[12];
    const float* icomp_wkv   = (const float*)d_in[13];
    const float* icomp_wgate = (const float*)d_in[14];
    const float* icomp_ape   = (const float*)d_in[15];
    const float* icomp_norm_w= (const float*)d_in[16];
    const float* attn_sink   = (const float*)d_in[17];
    const float* wo_a        = (const float*)d_in[18];
    const float* wo_b        = (const float*)d_in[19];
    const float* gate_up_w   = (const float*)d_in[20];
    const float* down_w      = (const float*)d_in[21];
    float* out = (float*)d_out;

    float *px, *pqr, *pq, *pqi, *pkvA, *pkvF, *pkvc;
    float *pikA, *pikF, *pki, *pkiT, *pwoaT, *piw, *pisc, *po, *poa, *ph, *px2, *pact;
    float *pRC, *pRS;
    int *pselidx, *pselcnt;
    cudaGetSymbolAddress((void**)&px,   g_x);
    cudaGetSymbolAddress((void**)&pqr,  g_qr);
    cudaGetSymbolAddress((void**)&pq,   g_q);
    cudaGetSymbolAddress((void**)&pqi,  g_qi);
    cudaGetSymbolAddress((void**)&pkvA, g_kvA);
    cudaGetSymbolAddress((void**)&pkvF, g_kvF);
    cudaGetSymbolAddress((void**)&pkvc, g_kvc);
    cudaGetSymbolAddress((void**)&pikA, g_ikA);
    cudaGetSymbolAddress((void**)&pikF, g_ikF);
    cudaGetSymbolAddress((void**)&pki,  g_ki);
    cudaGetSymbolAddress((void**)&pkiT, g_kiT);
    cudaGetSymbolAddress((void**)&pwoaT,g_woaT);
    cudaGetSymbolAddress((void**)&piw,  g_iw);
    cudaGetSymbolAddress((void**)&pisc, g_isc);
    cudaGetSymbolAddress((void**)&pselidx, g_selidx);
    cudaGetSymbolAddress((void**)&pselcnt, g_selcnt);
    cudaGetSymbolAddress((void**)&po,   g_o);
    cudaGetSymbolAddress((void**)&poa,  g_oa);
    cudaGetSymbolAddress((void**)&ph,   g_h);
    cudaGetSymbolAddress((void**)&px2,  g_x2);
    cudaGetSymbolAddress((void**)&pact, g_act);
    cudaGetSymbolAddress((void**)&pRC,  g_ropeC);
    cudaGetSymbolAddress((void**)&pRS,  g_ropeS);

    cudaFuncSetAttribute(tgemm_kernel<EP_NONE>,  cudaFuncAttributeMaxDynamicSharedMemorySize, SMEM_PIPE_BYTES);
    cudaFuncSetAttribute(tgemm_kernel<EP_ADD>,   cudaFuncAttributeMaxDynamicSharedMemorySize, SMEM_PIPE_BYTES);
    cudaFuncSetAttribute(tgemm_kernel<EP_GATE>,  cudaFuncAttributeMaxDynamicSharedMemorySize, SMEM_PIPE_BYTES);
    cudaFuncSetAttribute(tgemm_kernel<EP_SILU>,  cudaFuncAttributeMaxDynamicSharedMemorySize, SMEM_PIPE_BYTES);
    cudaFuncSetAttribute(tgemm_kernel<EP_RFUSE>, cudaFuncAttributeMaxDynamicSharedMemorySize, SMEM_PIPE_BYTES);

    // 0) rope table
    rope_table_kernel<<<(T_ * 32 + 255) / 256, 256>>>(pRC, pRS);

    // 1) x = rms(hidden, ln1)
    rms_kernel<<<T_, 256>>>(hidden, ln1_w, px, DIM_);

    // 2) qr = rms(x @ wq_a, q_norm)
    tgemm_kernel<EP_NONE><<<ggrid(T_, QL_), 256, SMEM_PIPE_BYTES>>>(T_, QL_, DIM_, px, DIM_, wq_a, QL_, nullptr, nullptr, pqr, QL_);
    rms_kernel<<<T_, 256>>>(pqr, q_norm_w, pqr, QL_);

    // 3) q / qi projections + rope
    tgemm_kernel<EP_NONE><<<ggrid(T_, H_*DH_), 256, SMEM_PIPE_BYTES>>>(T_, H_*DH_, QL_, pqr, QL_, wq_b, H_*DH_, nullptr, nullptr, pq, H_*DH_);
    tgemm_kernel<EP_NONE><<<ggrid(T_, HI_*DI_), 256, SMEM_PIPE_BYTES>>>(T_, HI_*DI_, QL_, pqr, QL_, idx_wq_b, HI_*DI_, nullptr, nullptr, pqi, HI_*DI_);
    rope_apply_kernel<<<T_ * H_ / 8,  256>>>(pq,  positions, pRC, pRS, H_,  DH_, NOPE_,  0, T_ * H_);
    rope_apply_kernel<<<T_ * HI_ / 8, 256>>>(pqi, positions, pRC, pRS, HI_, DI_, INOPE_, 0, T_ * HI_);

    // 4) kvc: wkv GEMM, then wgate GEMM with fused sigmoid-gate + ape
    tgemm_kernel<EP_NONE><<<ggrid(T_, 2*DH_), 256, SMEM_PIPE_BYTES>>>(T_, 2*DH_, DIM_, px, DIM_, comp_wkv, 2*DH_, nullptr, nullptr, pkvA, 2*DH_);
    tgemm_kernel<EP_GATE><<<ggrid(T_, 2*DH_), 256, SMEM_PIPE_BYTES>>>(T_, 2*DH_, DIM_, px, DIM_, comp_wgate, 2*DH_, pkvA, comp_ape, pkvF, 2*DH_);
    compress_kernel<<<SC_, DH_>>>(pkvF, comp_norm_w, pkvc, DH_);
    rope_apply_kernel<<<SC_ / 8, 256>>>(pkvc, positions, pRC, pRS, 1, DH_, NOPE_, 1, SC_);

    // 5) ki: same fused pattern + rope + transpose
    tgemm_kernel<EP_NONE><<<ggrid(T_, 2*DI_), 256, SMEM_PIPE_BYTES>>>(T_, 2*DI_, DIM_, px, DIM_, icomp_wkv, 2*DI_, nullptr, nullptr, pikA, 2*DI_);
    tgemm_kernel<EP_GATE><<<ggrid(T_, 2*DI_), 256, SMEM_PIPE_BYTES>>>(T_, 2*DI_, DIM_, px, DIM_, icomp_wgate, 2*DI_, pikA, icomp_ape, pikF, 2*DI_);
    compress_kernel<<<SC_, DI_>>>(pikF, icomp_norm_w, pki, DI_);
    rope_apply_kernel<<<SC_ / 8, 256>>>(pki, positions, pRC, pRS, 1, DI_, INOPE_, 1, SC_);
    transpose_kernel<<<dim3(DI_/32, SC_/32, 1), dim3(32, 8)>>>(pki, pkiT, SC_, DI_);

    // 6) iw
    tgemm_kernel<EP_NONE><<<ggrid(T_, HI_), 256, SMEM_PIPE_BYTES>>>(T_, HI_, DIM_, px, DIM_, idx_wproj, HI_, nullptr, nullptr, piw, HI_);

    // 7) R GEMM with fused weighted-relu head reduction -> isc directly (R never materialized)
    tgemm_kernel<EP_RFUSE><<<ggrid(T_*HI_, SC_), 256, SMEM_PIPE_BYTES>>>(T_*HI_, SC_, DI_, pqi, DI_, pkiT, SC_, piw, nullptr, pisc, SC_);

    // 8) top-256
    topk_kernel<<<T_, 256>>>(pisc, pselidx, pselcnt);

    // 9) head-shared flash attention
    attn2_kernel<<<T_, 512>>>(pq, pkvc, pselidx, pselcnt, attn_sink, po);

    // 10) output proj
    transpose_kernel<<<dim3(FG_/32, OLORA_/32, G_), dim3(32, 8)>>>(wo_a, pwoaT, OLORA_, FG_);
    for (int g = 0; g < G_; g++) {
        tgemm_kernel<EP_NONE><<<ggrid(T_, OLORA_), 256, SMEM_PIPE_BYTES>>>(
            T_, OLORA_, FG_,
            po + g * FG_, H_*DH_,
            pwoaT + (size_t)g * FG_ * OLORA_, OLORA_,
            nullptr, nullptr, poa + g * OLORA_, G_*OLORA_);
    }
    tgemm_kernel<EP_ADD><<<ggrid(T_, DIM_), 256, SMEM_PIPE_BYTES>>>(T_, DIM_, G_*OLORA_, poa, G_*OLORA_, wo_b, DIM_, hidden, nullptr, ph, DIM_);

    // 11) MLP: gate GEMM -> act; up GEMM fused silu-mul (in place); down GEMM + residual
    rms_kernel<<<T_, 256>>>(ph, ln2_w, px2, DIM_);
    tgemm_kernel<EP_NONE><<<ggrid(T_, II_), 256, SMEM_PIPE_BYTES>>>(T_, II_, DIM_, px2, DIM_, gate_up_w, 2*II_, nullptr, nullptr, pact, II_);
    tgemm_kernel<EP_SILU><<<ggrid(T_, II_), 256, SMEM_PIPE_BYTES>>>(T_, II_, DIM_, px2, DIM_, gate_up_w + II_, 2*II_, pact, nullptr, pact, II_);
    tgemm_kernel<EP_ADD><<<ggrid(T_, DIM_), 256, SMEM_PIPE_BYTES>>>(T_, DIM_, II_, pact, II_, down_w, DIM_, ph, nullptr, out, DIM_);
}